// round 6
// baseline (speedup 1.0000x reference)
#include <cuda_runtime.h>
#include <cstdint>

#define B_   4
#define N_   4096
#define CIN  256
#define CK   128
#define COUT 256

// ---------------- scratch (no allocs allowed) ----------------
__device__ float g_q[B_ * N_ * CK];    // [b][n][128]
__device__ float g_k[B_ * N_ * CK];    // [b][n][128]
__device__ float g_v[B_ * N_ * CK];    // [b][n][128]
__device__ float g_ctx[B_ * N_ * CK];  // [b][n][128]
__device__ float g_wq[CK * CIN];
__device__ float g_wk[CK * CIN];
__device__ float g_bq[CK];
__device__ float g_bk[CK];

// ================= helpers =================
__device__ __forceinline__ uint32_t f2tf32(float f) {
    uint32_t u;
    asm("cvt.rna.tf32.f32 %0, %1;" : "=r"(u) : "f"(f));
    return u;
}
__device__ __forceinline__ void mma_tf32(float* d, uint32_t a0, uint32_t a1,
                                         uint32_t a2, uint32_t a3,
                                         uint32_t b0, uint32_t b1) {
    asm volatile(
        "mma.sync.aligned.m16n8k8.row.col.f32.tf32.tf32.f32 "
        "{%0,%1,%2,%3}, {%4,%5,%6,%7}, {%8,%9}, {%0,%1,%2,%3};"
        : "+f"(d[0]), "+f"(d[1]), "+f"(d[2]), "+f"(d[3])
        : "r"(a0), "r"(a1), "r"(a2), "r"(a3), "r"(b0), "r"(b1));
}

// ---------------- BN folding ----------------
__global__ void prep_kernel(const float* __restrict__ wk, const float* __restrict__ bk,
                            const float* __restrict__ gk, const float* __restrict__ betak,
                            const float* __restrict__ mk, const float* __restrict__ vk,
                            const float* __restrict__ wq, const float* __restrict__ bq,
                            const float* __restrict__ gq, const float* __restrict__ betaq,
                            const float* __restrict__ mq, const float* __restrict__ vq) {
    int idx = blockIdx.x * blockDim.x + threadIdx.x;
    if (idx >= CK * CIN) return;
    int o = idx / CIN;
    float sk = gk[o] * rsqrtf(vk[o] + 1e-5f);
    float sq = gq[o] * rsqrtf(vq[o] + 1e-5f);
    g_wk[idx] = wk[idx] * sk;
    g_wq[idx] = wq[idx] * sq;
    if ((idx % CIN) == 0) {
        g_bk[o] = (bk[o] - mk[o]) * sk + betak[o];
        g_bq[o] = (bq[o] - mq[o]) * sq + betaq[o];
    }
}

// ======== fused 3-way projection GEMM ========
// Stage A (X) in registers only; W loaded direct (L2-hot). 2 CTAs/SM.
#define PJ_APAD 132
#define PJ_BPAD 72
#define PJ_SMEM ((64 * PJ_APAD + 128 * PJ_BPAD) * 4)

__global__ __launch_bounds__(256, 2) void gemm_tc_proj3(
    const float* __restrict__ xdec, const float* __restrict__ xenc,
    const float* __restrict__ wq, const float* __restrict__ wk,
    const float* __restrict__ wv,
    const float* __restrict__ bq, const float* __restrict__ bk,
    const float* __restrict__ bv,
    float* __restrict__ yq, float* __restrict__ yk, float* __restrict__ yv) {
    extern __shared__ uint32_t dsm[];
    uint32_t* As = dsm;                 // [64 c][132 n] tf32
    uint32_t* Bs = dsm + 64 * PJ_APAD;  // [128 o][72 interleaved c] tf32

    int which = blockIdx.y;
    const float* X = (which == 0) ? xdec : xenc;
    const float* W = (which == 0) ? wq : (which == 1) ? wk : wv;
    const float* bias = (which == 0) ? bq : (which == 1) ? bk : bv;
    float* Y = (which == 0) ? yq : (which == 1) ? yk : yv;
    int relu = (which < 2);

    int b = blockIdx.z;
    int n0 = blockIdx.x * 128;
    const float* Xb = X + (size_t)b * CIN * N_;
    float* Yb = Y + (size_t)b * (size_t)N_ * CK;

    int tid = threadIdx.x;
    int w = tid >> 5, lane = tid & 31;
    int r4 = lane >> 2, c4 = lane & 3;

    float accD[16][4];
#pragma unroll
    for (int i = 0; i < 16; ++i)
#pragma unroll
        for (int j = 0; j < 4; ++j) accD[i][j] = 0.f;

    // prefetch A chunk only (8 float4/thread)
    float4 ra[8];
#pragma unroll
    for (int i = 0; i < 8; ++i) {
        int idx = tid + i * 256;
        int cc = idx >> 5, nq = idx & 31;
        ra[i] = *(const float4*)(Xb + (size_t)cc * N_ + n0 + nq * 4);
    }

    for (int c0 = 0; c0 < CIN; c0 += 64) {
        __syncthreads();  // previous chunk's MMAs done reading smem
#pragma unroll
        for (int i = 0; i < 8; ++i) {
            int idx = tid + i * 256;
            int cc = idx >> 5, nq = idx & 31;
            uint4 u;
            u.x = f2tf32(ra[i].x); u.y = f2tf32(ra[i].y);
            u.z = f2tf32(ra[i].z); u.w = f2tf32(ra[i].w);
            *(uint4*)(As + cc * PJ_APAD + nq * 4) = u;
        }
        // W chunk: direct load -> cvt -> STS (L2-resident weight)
#pragma unroll
        for (int i = 0; i < 8; ++i) {
            int idx = tid + i * 256;
            int oo = idx >> 4, cq = idx & 15;
            float4 v = *(const float4*)(W + (size_t)oo * CIN + c0 + cq * 4);
            uint32_t* dst = Bs + oo * PJ_BPAD + (cq >> 1) * 8 + (cq & 1);
            dst[0] = f2tf32(v.x); dst[2] = f2tf32(v.y);
            dst[4] = f2tf32(v.z); dst[6] = f2tf32(v.w);
        }
        __syncthreads();

        if (c0 + 64 < CIN) {  // prefetch next A chunk; overlaps MMAs below
#pragma unroll
            for (int i = 0; i < 8; ++i) {
                int idx = tid + i * 256;
                int cc = idx >> 5, nq = idx & 31;
                ra[i] = *(const float4*)(Xb + (size_t)(c0 + 64 + cc) * N_ + n0 + nq * 4);
            }
        }

#pragma unroll
        for (int kk = 0; kk < 8; ++kk) {
            uint32_t a0 = As[(kk * 8 + c4) * PJ_APAD + w * 16 + r4];
            uint32_t a1 = As[(kk * 8 + c4) * PJ_APAD + w * 16 + r4 + 8];
            uint32_t a2 = As[(kk * 8 + c4 + 4) * PJ_APAD + w * 16 + r4];
            uint32_t a3 = As[(kk * 8 + c4 + 4) * PJ_APAD + w * 16 + r4 + 8];
#pragma unroll
            for (int nf = 0; nf < 16; ++nf) {
                uint2 bf = *(const uint2*)(Bs + (nf * 8 + r4) * PJ_BPAD + kk * 8 + 2 * c4);
                mma_tf32(accD[nf], a0, a1, a2, a3, bf.x, bf.y);
            }
        }
    }

    int nlo = n0 + w * 16 + r4;
#pragma unroll
    for (int nf = 0; nf < 16; ++nf) {
        int o = nf * 8 + 2 * c4;
        float b0 = __ldg(bias + o), b1 = __ldg(bias + o + 1);
        float2 lo, hi;
        lo.x = accD[nf][0] + b0; lo.y = accD[nf][1] + b1;
        hi.x = accD[nf][2] + b0; hi.y = accD[nf][3] + b1;
        if (relu) {
            lo.x = fmaxf(lo.x, 0.f); lo.y = fmaxf(lo.y, 0.f);
            hi.x = fmaxf(hi.x, 0.f); hi.y = fmaxf(hi.y, 0.f);
        }
        *(float2*)(Yb + (size_t)nlo * CK + o) = lo;
        *(float2*)(Yb + (size_t)(nlo + 8) * CK + o) = hi;
    }
}

// ======== tensor-core output GEMM ========
// Stage CTX (streaming) in registers; WO direct (L2-hot). 2 CTAs/SM.
#define GO_PAD 72
#define GO_SMEM ((128 * GO_PAD * 2) * 4)

__global__ __launch_bounds__(256, 2) void gemm_tc_out(
    const float* __restrict__ CTX, const float* __restrict__ WO,
    const float* __restrict__ bo, float* __restrict__ Y) {
    extern __shared__ uint32_t dsm[];
    uint32_t* As = dsm;                // [128 o][72] WO
    uint32_t* Bs = dsm + 128 * GO_PAD; // [128 n][72] CTX

    int b = blockIdx.z;
    int n0 = blockIdx.x * 128, o0 = blockIdx.y * 128;
    const float* Cb = CTX + (size_t)b * N_ * CK;
    float* Yb = Y + (size_t)b * (size_t)COUT * N_;

    int tid = threadIdx.x;
    int w = tid >> 5, lane = tid & 31;
    int r4 = lane >> 2, c4 = lane & 3;

    float accD[16][4];
#pragma unroll
    for (int i = 0; i < 16; ++i)
#pragma unroll
        for (int j = 0; j < 4; ++j) accD[i][j] = 0.f;

    float4 rb[8];
#pragma unroll
    for (int i = 0; i < 8; ++i) {
        int idx = tid + i * 256;
        int nn = idx >> 4, cq = idx & 15;
        rb[i] = *(const float4*)(Cb + (size_t)(n0 + nn) * CK + cq * 4);
    }

    for (int c0 = 0; c0 < CK; c0 += 64) {
        __syncthreads();
#pragma unroll
        for (int i = 0; i < 8; ++i) {
            int idx = tid + i * 256;
            int nn = idx >> 4, cq = idx & 15;
            uint32_t* dstb = Bs + nn * GO_PAD + (cq >> 1) * 8 + (cq & 1);
            dstb[0] = f2tf32(rb[i].x); dstb[2] = f2tf32(rb[i].y);
            dstb[4] = f2tf32(rb[i].z); dstb[6] = f2tf32(rb[i].w);
        }
#pragma unroll
        for (int i = 0; i < 8; ++i) {
            int idx = tid + i * 256;
            int oo = idx >> 4, cq = idx & 15;
            float4 v = *(const float4*)(WO + (size_t)(o0 + oo) * CK + c0 + cq * 4);
            uint32_t* dsta = As + oo * GO_PAD + (cq >> 1) * 8 + (cq & 1);
            dsta[0] = f2tf32(v.x); dsta[2] = f2tf32(v.y);
            dsta[4] = f2tf32(v.z); dsta[6] = f2tf32(v.w);
        }
        __syncthreads();

        if (c0 + 64 < CK) {
#pragma unroll
            for (int i = 0; i < 8; ++i) {
                int idx = tid + i * 256;
                int nn = idx >> 4, cq = idx & 15;
                rb[i] = *(const float4*)(Cb + (size_t)(n0 + nn) * CK + c0 + 64 + cq * 4);
            }
        }

#pragma unroll
        for (int kk = 0; kk < 8; ++kk) {
            uint2 a02 = *(const uint2*)(As + (w * 16 + r4) * GO_PAD + kk * 8 + 2 * c4);
            uint2 a13 = *(const uint2*)(As + (w * 16 + r4 + 8) * GO_PAD + kk * 8 + 2 * c4);
#pragma unroll
            for (int nf = 0; nf < 16; ++nf) {
                uint2 bf = *(const uint2*)(Bs + (nf * 8 + r4) * GO_PAD + kk * 8 + 2 * c4);
                mma_tf32(accD[nf], a02.x, a13.x, a02.y, a13.y, bf.x, bf.y);
            }
        }
    }

    int olo = o0 + w * 16 + r4;
    float blo = __ldg(bo + olo), bhi = __ldg(bo + olo + 8);
#pragma unroll
    for (int nf = 0; nf < 16; ++nf) {
        int n = n0 + nf * 8 + 2 * c4;
        float2 lo, hi;
        lo.x = accD[nf][0] + blo; lo.y = accD[nf][1] + blo;
        hi.x = accD[nf][2] + bhi; hi.y = accD[nf][3] + bhi;
        *(float2*)(Yb + (size_t)olo * N_ + n) = lo;
        *(float2*)(Yb + (size_t)(olo + 8) * N_ + n) = hi;
    }
}

// ---------------- mma.sync tf32 flash attention ----------------
// 128 queries/CTA, 4 warps x 32 rows. Loads interleaved in 4-float4 batches
// between MMA groups: LDG batch -> MMA group (latency cover) -> cvt+STS batch.
#define QPAD 132
#define KPAD 132
#define VPAD 136
#define PPAD 68
#define OFF_K (128 * QPAD)
#define OFF_V (OFF_K + 64 * KPAD)
#define OFF_P (OFF_V + 64 * VPAD)
#define SMEM_FLASH ((OFF_P + 128 * PPAD) * 4)

__global__ __launch_bounds__(128, 1) void flash_mma(
    const float* __restrict__ Q, const float* __restrict__ K,
    const float* __restrict__ V, float* __restrict__ CTX) {
    extern __shared__ uint32_t sm[];
    uint32_t* Qs = sm;
    uint32_t* Ks = sm + OFF_K;
    uint32_t* Vs = sm + OFF_V;
    uint32_t* Ps = sm + OFF_P;

    int tid = threadIdx.x;
    int w = tid >> 5, lane = tid & 31;
    int r4 = lane >> 2, c4 = lane & 3;
    int b = blockIdx.y;
    int q0 = blockIdx.x * 128;
    const float4* Qg = (const float4*)(Q + ((size_t)b * N_ + q0) * CK);
    const float* Kb = K + (size_t)b * N_ * CK;
    const float* Vb = V + (size_t)b * N_ * CK;

    // prologue: Q (scale + tf32) and K(0)
    {
        const float sc = 0.08838834764831845f;  // 1/sqrt(128)
        for (int idx = tid; idx < 128 * 32; idx += 128) {
            int r = idx >> 5, c = idx & 31;
            float4 v = Qg[idx];
            uint32_t* dst = Qs + r * QPAD + c * 4;
            dst[0] = f2tf32(v.x * sc);
            dst[1] = f2tf32(v.y * sc);
            dst[2] = f2tf32(v.z * sc);
            dst[3] = f2tf32(v.w * sc);
        }
        const float4* Kg = (const float4*)Kb;
        for (int idx = tid; idx < 64 * 32; idx += 128) {
            int r = idx >> 5, c = idx & 31;
            float4 kv = Kg[idx];
            uint32_t* kd = Ks + r * KPAD + c * 4;
            kd[0] = f2tf32(kv.x); kd[1] = f2tf32(kv.y);
            kd[2] = f2tf32(kv.z); kd[3] = f2tf32(kv.w);
        }
    }
    __syncthreads();

    float accO[2][16][4];
#pragma unroll
    for (int rb = 0; rb < 2; ++rb)
#pragma unroll
        for (int i = 0; i < 16; ++i)
#pragma unroll
            for (int j = 0; j < 4; ++j) accO[rb][i][j] = 0.f;
    float l_lo[2] = {0.f, 0.f}, l_hi[2] = {0.f, 0.f};

    const uint32_t* qbase = Qs + (w * 32) * QPAD;
    uint32_t* pbase = Ps + (w * 32) * PPAD;

    for (int t = 0; t < N_ / 64; ++t) {
        const float4* Vg = (const float4*)(Vb + (size_t)(t * 64) * CK);

        // ---- Phase S: S = Q.K^T with V(t) load batches interleaved ----
        float accS[2][8][4];
#pragma unroll
        for (int rb = 0; rb < 2; ++rb)
#pragma unroll
            for (int i = 0; i < 8; ++i)
#pragma unroll
                for (int j = 0; j < 4; ++j) accS[rb][i][j] = 0.f;

#pragma unroll
        for (int g = 0; g < 4; ++g) {
            // issue V batch g (4 float4/thread); MMAs below cover the latency
            float4 vst[4];
#pragma unroll
            for (int i = 0; i < 4; ++i) vst[i] = Vg[tid + (g * 4 + i) * 128];

#pragma unroll
            for (int kq = 0; kq < 4; ++kq) {
                int kk = g * 4 + kq;
                uint32_t a[2][4];
#pragma unroll
                for (int rb = 0; rb < 2; ++rb) {
                    const uint32_t* qb = qbase + (rb * 16) * QPAD;
                    a[rb][0] = qb[r4 * QPAD + kk * 8 + c4];
                    a[rb][1] = qb[(r4 + 8) * QPAD + kk * 8 + c4];
                    a[rb][2] = qb[r4 * QPAD + kk * 8 + c4 + 4];
                    a[rb][3] = qb[(r4 + 8) * QPAD + kk * 8 + c4 + 4];
                }
#pragma unroll
                for (int nf = 0; nf < 8; ++nf) {
                    uint32_t b0 = Ks[(nf * 8 + r4) * KPAD + kk * 8 + c4];
                    uint32_t b1 = Ks[(nf * 8 + r4) * KPAD + kk * 8 + c4 + 4];
                    mma_tf32(accS[0][nf], a[0][0], a[0][1], a[0][2], a[0][3], b0, b1);
                    mma_tf32(accS[1][nf], a[1][0], a[1][1], a[1][2], a[1][3], b0, b1);
                }
            }

            // store V batch g
#pragma unroll
            for (int i = 0; i < 4; ++i) {
                int idx = tid + (g * 4 + i) * 128;
                int r = idx >> 5, c = idx & 31;
                uint32_t* vd = Vs + r * VPAD + c * 4;
                vd[0] = f2tf32(vst[i].x); vd[1] = f2tf32(vst[i].y);
                vd[2] = f2tf32(vst[i].z); vd[3] = f2tf32(vst[i].w);
            }
        }

        // P = exp(S - 4); write to smem (tf32); accumulate row sums
#pragma unroll
        for (int rb = 0; rb < 2; ++rb) {
            uint32_t* pb = pbase + (rb * 16) * PPAD;
            float slo = 0.f, shi = 0.f;
#pragma unroll
            for (int nf = 0; nf < 8; ++nf) {
                float p0 = __expf(accS[rb][nf][0] - 4.f);
                float p1 = __expf(accS[rb][nf][1] - 4.f);
                float p2 = __expf(accS[rb][nf][2] - 4.f);
                float p3 = __expf(accS[rb][nf][3] - 4.f);
                slo += p0 + p1;
                shi += p2 + p3;
                uint2 lo; lo.x = f2tf32(p0); lo.y = f2tf32(p1);
                uint2 hi; hi.x = f2tf32(p2); hi.y = f2tf32(p3);
                *(uint2*)(pb + r4 * PPAD + nf * 8 + 2 * c4) = lo;
                *(uint2*)(pb + (r4 + 8) * PPAD + nf * 8 + 2 * c4) = hi;
            }
            slo += __shfl_xor_sync(0xffffffffu, slo, 1);
            slo += __shfl_xor_sync(0xffffffffu, slo, 2);
            shi += __shfl_xor_sync(0xffffffffu, shi, 1);
            shi += __shfl_xor_sync(0xffffffffu, shi, 2);
            l_lo[rb] += slo;
            l_hi[rb] += shi;
        }

        __syncthreads();  // B1: V stores visible; all warps done reading Ks

        // ---- Phase PV: O += P.V with K(t+1) load batches interleaved ----
        const float4* Kg = (const float4*)(Kb + (size_t)((t + 1) * 64) * CK);
        bool more = (t + 1 < N_ / 64);

#pragma unroll
        for (int g = 0; g < 4; ++g) {
            float4 kst[4];
            if (more) {
#pragma unroll
                for (int i = 0; i < 4; ++i) kst[i] = Kg[tid + (g * 4 + i) * 128];
            }

#pragma unroll
            for (int kq = 0; kq < 2; ++kq) {
                int kk = g * 2 + kq;
                uint32_t a[2][4];
#pragma unroll
                for (int rb = 0; rb < 2; ++rb) {
                    const uint32_t* pb = pbase + (rb * 16) * PPAD;
                    a[rb][0] = pb[r4 * PPAD + kk * 8 + c4];
                    a[rb][1] = pb[(r4 + 8) * PPAD + kk * 8 + c4];
                    a[rb][2] = pb[r4 * PPAD + kk * 8 + c4 + 4];
                    a[rb][3] = pb[(r4 + 8) * PPAD + kk * 8 + c4 + 4];
                }
#pragma unroll
                for (int nf = 0; nf < 16; ++nf) {
                    uint32_t b0 = Vs[(kk * 8 + c4) * VPAD + nf * 8 + r4];
                    uint32_t b1 = Vs[(kk * 8 + c4 + 4) * VPAD + nf * 8 + r4];
                    mma_tf32(accO[0][nf], a[0][0], a[0][1], a[0][2], a[0][3], b0, b1);
                    mma_tf32(accO[1][nf], a[1][0], a[1][1], a[1][2], a[1][3], b0, b1);
                }
            }

            if (more) {
#pragma unroll
                for (int i = 0; i < 4; ++i) {
                    int idx = tid + (g * 4 + i) * 128;
                    int r = idx >> 5, c = idx & 31;
                    uint32_t* kd = Ks + r * KPAD + c * 4;
                    kd[0] = f2tf32(kst[i].x); kd[1] = f2tf32(kst[i].y);
                    kd[2] = f2tf32(kst[i].z); kd[3] = f2tf32(kst[i].w);
                }
            }
        }

        __syncthreads();  // B2: K stores visible; all warps done reading Vs
    }

    // normalize + store
#pragma unroll
    for (int rb = 0; rb < 2; ++rb) {
        float invlo = 1.f / l_lo[rb], invhi = 1.f / l_hi[rb];
        float* outlo = CTX + ((size_t)b * N_ + q0 + w * 32 + rb * 16 + r4) * CK;
        float* outhi = outlo + 8 * CK;
#pragma unroll
        for (int nf = 0; nf < 16; ++nf) {
            float2 lo; lo.x = accO[rb][nf][0] * invlo; lo.y = accO[rb][nf][1] * invlo;
            float2 hi; hi.x = accO[rb][nf][2] * invhi; hi.y = accO[rb][nf][3] * invhi;
            *(float2*)(outlo + nf * 8 + 2 * c4) = lo;
            *(float2*)(outhi + nf * 8 + 2 * c4) = hi;
        }
    }
}

// ---------------- launch ----------------
extern "C" void kernel_launch(void* const* d_in, const int* in_sizes, int n_in,
                              void* d_out, int out_size) {
    const float* x_enc = (const float*)d_in[0];
    const float* x_dec = (const float*)d_in[1];
    const float* wk    = (const float*)d_in[2];
    const float* bk    = (const float*)d_in[3];
    const float* gk    = (const float*)d_in[4];
    const float* betak = (const float*)d_in[5];
    const float* mk    = (const float*)d_in[6];
    const float* vk    = (const float*)d_in[7];
    const float* wq    = (const float*)d_in[8];
    const float* bq    = (const float*)d_in[9];
    const float* gq    = (const float*)d_in[10];
    const float* betaq = (const float*)d_in[11];
    const float* mq    = (const float*)d_in[12];
    const float* vq    = (const float*)d_in[13];
    const float* wv    = (const float*)d_in[14];
    const float* bv    = (const float*)d_in[15];
    const float* wo    = (const float*)d_in[16];
    const float* bo    = (const float*)d_in[17];
    float* out = (float*)d_out;

    float *pq, *pk, *pv, *pctx, *pwq, *pwk, *pbq, *pbk;
    cudaGetSymbolAddress((void**)&pq, g_q);
    cudaGetSymbolAddress((void**)&pk, g_k);
    cudaGetSymbolAddress((void**)&pv, g_v);
    cudaGetSymbolAddress((void**)&pctx, g_ctx);
    cudaGetSymbolAddress((void**)&pwq, g_wq);
    cudaGetSymbolAddress((void**)&pwk, g_wk);
    cudaGetSymbolAddress((void**)&pbq, g_bq);
    cudaGetSymbolAddress((void**)&pbk, g_bk);

    prep_kernel<<<(CK * CIN + 255) / 256, 256>>>(wk, bk, gk, betak, mk, vk,
                                                 wq, bq, gq, betaq, mq, vq);

    cudaFuncSetAttribute(gemm_tc_proj3, cudaFuncAttributeMaxDynamicSharedMemorySize, PJ_SMEM);
    cudaFuncSetAttribute(gemm_tc_out, cudaFuncAttributeMaxDynamicSharedMemorySize, GO_SMEM);
    cudaFuncSetAttribute(flash_mma, cudaFuncAttributeMaxDynamicSharedMemorySize, SMEM_FLASH);

    gemm_tc_proj3<<<dim3(N_ / 128, 3, B_), 256, PJ_SMEM>>>(
        x_dec, x_enc, pwq, pwk, wv, pbq, pbk, bv, pq, pk, pv);

    flash_mma<<<dim3(N_ / 128, B_), 128, SMEM_FLASH>>>(pq, pk, pv, pctx);

    gemm_tc_out<<<dim3(N_ / 128, COUT / 128, B_), 256, GO_SMEM>>>(pctx, wo, bo, out);
}

// round 7
// speedup vs baseline: 1.1978x; 1.1978x over previous
#include <cuda_runtime.h>
#include <cstdint>

#define B_   4
#define N_   4096
#define CIN  256
#define CK   128
#define COUT 256

// ---------------- scratch (no allocs allowed) ----------------
__device__ float g_q[B_ * N_ * CK];    // [b][n][128]
__device__ float g_k[B_ * N_ * CK];    // [b][n][128]
__device__ float g_v[B_ * N_ * CK];    // [b][n][128]
__device__ float g_ctx[B_ * N_ * CK];  // [b][n][128]
__device__ float g_wq[CK * CIN];
__device__ float g_wk[CK * CIN];
__device__ float g_bq[CK];
__device__ float g_bk[CK];

// ================= helpers =================
__device__ __forceinline__ uint32_t f2tf32(float f) {
    uint32_t u;
    asm("cvt.rna.tf32.f32 %0, %1;" : "=r"(u) : "f"(f));
    return u;
}
__device__ __forceinline__ void mma_tf32(float* d, uint32_t a0, uint32_t a1,
                                         uint32_t a2, uint32_t a3,
                                         uint32_t b0, uint32_t b1) {
    asm volatile(
        "mma.sync.aligned.m16n8k8.row.col.f32.tf32.tf32.f32 "
        "{%0,%1,%2,%3}, {%4,%5,%6,%7}, {%8,%9}, {%0,%1,%2,%3};"
        : "+f"(d[0]), "+f"(d[1]), "+f"(d[2]), "+f"(d[3])
        : "r"(a0), "r"(a1), "r"(a2), "r"(a3), "r"(b0), "r"(b1));
}

// ---------------- BN folding ----------------
__global__ void prep_kernel(const float* __restrict__ wk, const float* __restrict__ bk,
                            const float* __restrict__ gk, const float* __restrict__ betak,
                            const float* __restrict__ mk, const float* __restrict__ vk,
                            const float* __restrict__ wq, const float* __restrict__ bq,
                            const float* __restrict__ gq, const float* __restrict__ betaq,
                            const float* __restrict__ mq, const float* __restrict__ vq) {
    int idx = blockIdx.x * blockDim.x + threadIdx.x;
    if (idx >= CK * CIN) return;
    int o = idx / CIN;
    float sk = gk[o] * rsqrtf(vk[o] + 1e-5f);
    float sq = gq[o] * rsqrtf(vq[o] + 1e-5f);
    g_wk[idx] = wk[idx] * sk;
    g_wq[idx] = wq[idx] * sq;
    if ((idx % CIN) == 0) {
        g_bk[o] = (bk[o] - mk[o]) * sk + betak[o];
        g_bq[o] = (bq[o] - mq[o]) * sq + betaq[o];
    }
}

// ======== fused 3-way projection GEMM (stage A, 2 CTAs/SM) ========
#define PJ_APAD 132
#define PJ_BPAD 72
#define PJ_SMEM ((64 * PJ_APAD + 128 * PJ_BPAD) * 4)

__global__ __launch_bounds__(256, 2) void gemm_tc_proj3(
    const float* __restrict__ xdec, const float* __restrict__ xenc,
    const float* __restrict__ wq, const float* __restrict__ wk,
    const float* __restrict__ wv,
    const float* __restrict__ bq, const float* __restrict__ bk,
    const float* __restrict__ bv,
    float* __restrict__ yq, float* __restrict__ yk, float* __restrict__ yv) {
    extern __shared__ uint32_t dsm[];
    uint32_t* As = dsm;                 // [64 c][132 n] tf32
    uint32_t* Bs = dsm + 64 * PJ_APAD;  // [128 o][72 interleaved c] tf32

    int which = blockIdx.y;
    const float* X = (which == 0) ? xdec : xenc;
    const float* W = (which == 0) ? wq : (which == 1) ? wk : wv;
    const float* bias = (which == 0) ? bq : (which == 1) ? bk : bv;
    float* Y = (which == 0) ? yq : (which == 1) ? yk : yv;
    int relu = (which < 2);

    int b = blockIdx.z;
    int n0 = blockIdx.x * 128;
    const float* Xb = X + (size_t)b * CIN * N_;
    float* Yb = Y + (size_t)b * (size_t)N_ * CK;

    int tid = threadIdx.x;
    int w = tid >> 5, lane = tid & 31;
    int r4 = lane >> 2, c4 = lane & 3;

    float accD[16][4];
#pragma unroll
    for (int i = 0; i < 16; ++i)
#pragma unroll
        for (int j = 0; j < 4; ++j) accD[i][j] = 0.f;

    float4 ra[8];
#pragma unroll
    for (int i = 0; i < 8; ++i) {
        int idx = tid + i * 256;
        int cc = idx >> 5, nq = idx & 31;
        ra[i] = *(const float4*)(Xb + (size_t)cc * N_ + n0 + nq * 4);
    }

    for (int c0 = 0; c0 < CIN; c0 += 64) {
        __syncthreads();
#pragma unroll
        for (int i = 0; i < 8; ++i) {
            int idx = tid + i * 256;
            int cc = idx >> 5, nq = idx & 31;
            uint4 u;
            u.x = f2tf32(ra[i].x); u.y = f2tf32(ra[i].y);
            u.z = f2tf32(ra[i].z); u.w = f2tf32(ra[i].w);
            *(uint4*)(As + cc * PJ_APAD + nq * 4) = u;
        }
#pragma unroll
        for (int i = 0; i < 8; ++i) {
            int idx = tid + i * 256;
            int oo = idx >> 4, cq = idx & 15;
            float4 v = *(const float4*)(W + (size_t)oo * CIN + c0 + cq * 4);
            uint32_t* dst = Bs + oo * PJ_BPAD + (cq >> 1) * 8 + (cq & 1);
            dst[0] = f2tf32(v.x); dst[2] = f2tf32(v.y);
            dst[4] = f2tf32(v.z); dst[6] = f2tf32(v.w);
        }
        __syncthreads();

        if (c0 + 64 < CIN) {
#pragma unroll
            for (int i = 0; i < 8; ++i) {
                int idx = tid + i * 256;
                int cc = idx >> 5, nq = idx & 31;
                ra[i] = *(const float4*)(Xb + (size_t)(c0 + 64 + cc) * N_ + n0 + nq * 4);
            }
        }

#pragma unroll
        for (int kk = 0; kk < 8; ++kk) {
            uint32_t a0 = As[(kk * 8 + c4) * PJ_APAD + w * 16 + r4];
            uint32_t a1 = As[(kk * 8 + c4) * PJ_APAD + w * 16 + r4 + 8];
            uint32_t a2 = As[(kk * 8 + c4 + 4) * PJ_APAD + w * 16 + r4];
            uint32_t a3 = As[(kk * 8 + c4 + 4) * PJ_APAD + w * 16 + r4 + 8];
#pragma unroll
            for (int nf = 0; nf < 16; ++nf) {
                uint2 bf = *(const uint2*)(Bs + (nf * 8 + r4) * PJ_BPAD + kk * 8 + 2 * c4);
                mma_tf32(accD[nf], a0, a1, a2, a3, bf.x, bf.y);
            }
        }
    }

    int nlo = n0 + w * 16 + r4;
#pragma unroll
    for (int nf = 0; nf < 16; ++nf) {
        int o = nf * 8 + 2 * c4;
        float b0 = __ldg(bias + o), b1 = __ldg(bias + o + 1);
        float2 lo, hi;
        lo.x = accD[nf][0] + b0; lo.y = accD[nf][1] + b1;
        hi.x = accD[nf][2] + b0; hi.y = accD[nf][3] + b1;
        if (relu) {
            lo.x = fmaxf(lo.x, 0.f); lo.y = fmaxf(lo.y, 0.f);
            hi.x = fmaxf(hi.x, 0.f); hi.y = fmaxf(hi.y, 0.f);
        }
        *(float2*)(Yb + (size_t)nlo * CK + o) = lo;
        *(float2*)(Yb + (size_t)(nlo + 8) * CK + o) = hi;
    }
}

// ======== tensor-core output GEMM (R5 version: stage both operands) ========
#define GO_PAD 72
#define GO_SMEM ((128 * GO_PAD * 2) * 4)

__global__ __launch_bounds__(256) void gemm_tc_out(
    const float* __restrict__ CTX, const float* __restrict__ WO,
    const float* __restrict__ bo, float* __restrict__ Y) {
    extern __shared__ uint32_t dsm[];
    uint32_t* As = dsm;                // [128 o][72] WO
    uint32_t* Bs = dsm + 128 * GO_PAD; // [128 n][72] CTX

    int b = blockIdx.z;
    int n0 = blockIdx.x * 128, o0 = blockIdx.y * 128;
    const float* Cb = CTX + (size_t)b * N_ * CK;
    float* Yb = Y + (size_t)b * (size_t)COUT * N_;

    int tid = threadIdx.x;
    int w = tid >> 5, lane = tid & 31;
    int r4 = lane >> 2, c4 = lane & 3;

    float accD[16][4];
#pragma unroll
    for (int i = 0; i < 16; ++i)
#pragma unroll
        for (int j = 0; j < 4; ++j) accD[i][j] = 0.f;

    float4 ra[8], rb[8];
#pragma unroll
    for (int i = 0; i < 8; ++i) {
        int idx = tid + i * 256;
        int oo = idx >> 4, cq = idx & 15;
        ra[i] = *(const float4*)(WO + (size_t)(o0 + oo) * CK + cq * 4);
        rb[i] = *(const float4*)(Cb + (size_t)(n0 + oo) * CK + cq * 4);
    }

    for (int c0 = 0; c0 < CK; c0 += 64) {
        __syncthreads();
#pragma unroll
        for (int i = 0; i < 8; ++i) {
            int idx = tid + i * 256;
            int oo = idx >> 4, cq = idx & 15;
            uint32_t* dsta = As + oo * GO_PAD + (cq >> 1) * 8 + (cq & 1);
            dsta[0] = f2tf32(ra[i].x); dsta[2] = f2tf32(ra[i].y);
            dsta[4] = f2tf32(ra[i].z); dsta[6] = f2tf32(ra[i].w);
            uint32_t* dstb = Bs + oo * GO_PAD + (cq >> 1) * 8 + (cq & 1);
            dstb[0] = f2tf32(rb[i].x); dstb[2] = f2tf32(rb[i].y);
            dstb[4] = f2tf32(rb[i].z); dstb[6] = f2tf32(rb[i].w);
        }
        __syncthreads();

        if (c0 + 64 < CK) {
#pragma unroll
            for (int i = 0; i < 8; ++i) {
                int idx = tid + i * 256;
                int oo = idx >> 4, cq = idx & 15;
                ra[i] = *(const float4*)(WO + (size_t)(o0 + oo) * CK + c0 + 64 + cq * 4);
                rb[i] = *(const float4*)(Cb + (size_t)(n0 + oo) * CK + c0 + 64 + cq * 4);
            }
        }

#pragma unroll
        for (int kk = 0; kk < 8; ++kk) {
            uint2 a02 = *(const uint2*)(As + (w * 16 + r4) * GO_PAD + kk * 8 + 2 * c4);
            uint2 a13 = *(const uint2*)(As + (w * 16 + r4 + 8) * GO_PAD + kk * 8 + 2 * c4);
#pragma unroll
            for (int nf = 0; nf < 16; ++nf) {
                uint2 bf = *(const uint2*)(Bs + (nf * 8 + r4) * GO_PAD + kk * 8 + 2 * c4);
                mma_tf32(accD[nf], a02.x, a13.x, a02.y, a13.y, bf.x, bf.y);
            }
        }
    }

    int olo = o0 + w * 16 + r4;
    float blo = __ldg(bo + olo), bhi = __ldg(bo + olo + 8);
#pragma unroll
    for (int nf = 0; nf < 16; ++nf) {
        int n = n0 + nf * 8 + 2 * c4;
        float2 lo, hi;
        lo.x = accD[nf][0] + blo; lo.y = accD[nf][1] + blo;
        hi.x = accD[nf][2] + bhi; hi.y = accD[nf][3] + bhi;
        *(float2*)(Yb + (size_t)olo * N_ + n) = lo;
        *(float2*)(Yb + (size_t)(olo + 8) * N_ + n) = hi;
    }
}

// ---------------- flash attention: key-split 8-warp layout ----------------
// 128 queries/CTA, 256 threads. Warp w: qgroup=w&3 (rows qgroup*32..+32),
// khalf=w>>2 (keys khalf*32..+32 of each 64-key tile). Crossbar traffic equals
// the 4-warp layout, but 2 warps/SMSP hide LDS/MUFU latency behind HMMA.
#define QPAD 132
#define KPAD 132
#define VPAD 136
#define PPAD 68
#define OFF_K (128 * QPAD)
#define OFF_V (OFF_K + 64 * KPAD)
#define OFF_P (OFF_V + 64 * VPAD)
#define SMEM_FLASH ((OFF_P + 128 * PPAD) * 4)

__global__ __launch_bounds__(256, 1) void flash_mma(
    const float* __restrict__ Q, const float* __restrict__ K,
    const float* __restrict__ V, float* __restrict__ CTX) {
    extern __shared__ uint32_t sm[];
    uint32_t* Qs = sm;
    uint32_t* Ks = sm + OFF_K;
    uint32_t* Vs = sm + OFF_V;
    uint32_t* Ps = sm + OFF_P;

    int tid = threadIdx.x;
    int w = tid >> 5, lane = tid & 31;
    int qgroup = w & 3, khalf = w >> 2;
    int r4 = lane >> 2, c4 = lane & 3;
    int b = blockIdx.y;
    int q0 = blockIdx.x * 128;
    const float4* Qg = (const float4*)(Q + ((size_t)b * N_ + q0) * CK);
    const float* Kb = K + (size_t)b * N_ * CK;
    const float* Vb = V + (size_t)b * N_ * CK;

    // load Q tile (scale + tf32)
    {
        const float sc = 0.08838834764831845f;  // 1/sqrt(128)
        for (int idx = tid; idx < 128 * 32; idx += 256) {
            int r = idx >> 5, c = idx & 31;
            float4 v = Qg[idx];
            uint32_t* dst = Qs + r * QPAD + c * 4;
            dst[0] = f2tf32(v.x * sc);
            dst[1] = f2tf32(v.y * sc);
            dst[2] = f2tf32(v.z * sc);
            dst[3] = f2tf32(v.w * sc);
        }
    }

    float accO[2][16][4];
#pragma unroll
    for (int rb = 0; rb < 2; ++rb)
#pragma unroll
        for (int i = 0; i < 16; ++i)
#pragma unroll
            for (int j = 0; j < 4; ++j) accO[rb][i][j] = 0.f;
    float l_lo[2] = {0.f, 0.f}, l_hi[2] = {0.f, 0.f};

    const uint32_t* qbase = Qs + (qgroup * 32) * QPAD;
    uint32_t* pbase = Ps + (qgroup * 32) * PPAD;
    const int kcol = khalf * 32;  // this warp's key-column base within tile

    for (int t = 0; t < N_ / 64; ++t) {
        __syncthreads();  // everyone done reading Ks (S) and Vs (PV) of t-1
        {
            const float4* Kg = (const float4*)(Kb + (size_t)(t * 64) * CK);
            const float4* Vg = (const float4*)(Vb + (size_t)(t * 64) * CK);
            for (int idx = tid; idx < 64 * 32; idx += 256) {
                int r = idx >> 5, c = idx & 31;
                float4 kv = Kg[idx];
                uint32_t* kd = Ks + r * KPAD + c * 4;
                kd[0] = f2tf32(kv.x); kd[1] = f2tf32(kv.y);
                kd[2] = f2tf32(kv.z); kd[3] = f2tf32(kv.w);
                float4 vv = Vg[idx];
                uint32_t* vd = Vs + r * VPAD + c * 4;
                vd[0] = f2tf32(vv.x); vd[1] = f2tf32(vv.y);
                vd[2] = f2tf32(vv.z); vd[3] = f2tf32(vv.w);
            }
        }
        __syncthreads();

        // S = Q . K^T over this warp's 32 keys (16 k-steps, 4 n-frags, 2 rowblocks)
        float accS[2][4][4];
#pragma unroll
        for (int rb = 0; rb < 2; ++rb)
#pragma unroll
            for (int i = 0; i < 4; ++i)
#pragma unroll
                for (int j = 0; j < 4; ++j) accS[rb][i][j] = 0.f;
#pragma unroll
        for (int kk = 0; kk < 16; ++kk) {
            uint32_t a[2][4];
#pragma unroll
            for (int rb = 0; rb < 2; ++rb) {
                const uint32_t* qb = qbase + (rb * 16) * QPAD;
                a[rb][0] = qb[r4 * QPAD + kk * 8 + c4];
                a[rb][1] = qb[(r4 + 8) * QPAD + kk * 8 + c4];
                a[rb][2] = qb[r4 * QPAD + kk * 8 + c4 + 4];
                a[rb][3] = qb[(r4 + 8) * QPAD + kk * 8 + c4 + 4];
            }
#pragma unroll
            for (int nf = 0; nf < 4; ++nf) {
                uint32_t b0 = Ks[(kcol + nf * 8 + r4) * KPAD + kk * 8 + c4];
                uint32_t b1 = Ks[(kcol + nf * 8 + r4) * KPAD + kk * 8 + c4 + 4];
                mma_tf32(accS[0][nf], a[0][0], a[0][1], a[0][2], a[0][3], b0, b1);
                mma_tf32(accS[1][nf], a[1][0], a[1][1], a[1][2], a[1][3], b0, b1);
            }
        }

        // P = exp(S - 4) into this warp's private [32 rows][32 cols] region
#pragma unroll
        for (int rb = 0; rb < 2; ++rb) {
            uint32_t* pb = pbase + (rb * 16) * PPAD;
            float slo = 0.f, shi = 0.f;
#pragma unroll
            for (int nf = 0; nf < 4; ++nf) {
                float p0 = __expf(accS[rb][nf][0] - 4.f);
                float p1 = __expf(accS[rb][nf][1] - 4.f);
                float p2 = __expf(accS[rb][nf][2] - 4.f);
                float p3 = __expf(accS[rb][nf][3] - 4.f);
                slo += p0 + p1;
                shi += p2 + p3;
                uint2 lo; lo.x = f2tf32(p0); lo.y = f2tf32(p1);
                uint2 hi; hi.x = f2tf32(p2); hi.y = f2tf32(p3);
                *(uint2*)(pb + r4 * PPAD + kcol + nf * 8 + 2 * c4) = lo;
                *(uint2*)(pb + (r4 + 8) * PPAD + kcol + nf * 8 + 2 * c4) = hi;
            }
            slo += __shfl_xor_sync(0xffffffffu, slo, 1);
            slo += __shfl_xor_sync(0xffffffffu, slo, 2);
            shi += __shfl_xor_sync(0xffffffffu, shi, 1);
            shi += __shfl_xor_sync(0xffffffffu, shi, 2);
            l_lo[rb] += slo;
            l_hi[rb] += shi;
        }
        __syncwarp();  // P region is warp-private

        // O += P . V over this warp's 32 keys (4 k-steps, 16 n-frags, 2 rowblocks)
#pragma unroll
        for (int kk = 0; kk < 4; ++kk) {
            uint32_t a[2][4];
#pragma unroll
            for (int rb = 0; rb < 2; ++rb) {
                const uint32_t* pb = pbase + (rb * 16) * PPAD;
                a[rb][0] = pb[r4 * PPAD + kcol + kk * 8 + c4];
                a[rb][1] = pb[(r4 + 8) * PPAD + kcol + kk * 8 + c4];
                a[rb][2] = pb[r4 * PPAD + kcol + kk * 8 + c4 + 4];
                a[rb][3] = pb[(r4 + 8) * PPAD + kcol + kk * 8 + c4 + 4];
            }
#pragma unroll
            for (int nf = 0; nf < 16; ++nf) {
                uint32_t b0 = Vs[(kcol + kk * 8 + c4) * VPAD + nf * 8 + r4];
                uint32_t b1 = Vs[(kcol + kk * 8 + c4 + 4) * VPAD + nf * 8 + r4];
                mma_tf32(accO[0][nf], a[0][0], a[0][1], a[0][2], a[0][3], b0, b1);
                mma_tf32(accO[1][nf], a[1][0], a[1][1], a[1][2], a[1][3], b0, b1);
            }
        }
    }

    // ---- merge key-halves: khalf=1 dumps partials to smem, khalf=0 combines ----
    __syncthreads();  // all compute done; Qs/Ks reusable
    float* Od = (float*)Qs;  // [128 rows][132] partial O from khalf=1
    float* Ld = (float*)Ks;  // [128] partial l from khalf=1
    if (khalf == 1) {
#pragma unroll
        for (int rb = 0; rb < 2; ++rb) {
            int row0 = qgroup * 32 + rb * 16 + r4;
            int row1 = row0 + 8;
#pragma unroll
            for (int nf = 0; nf < 16; ++nf) {
                float2 lo; lo.x = accO[rb][nf][0]; lo.y = accO[rb][nf][1];
                float2 hi; hi.x = accO[rb][nf][2]; hi.y = accO[rb][nf][3];
                *(float2*)(Od + row0 * 132 + nf * 8 + 2 * c4) = lo;
                *(float2*)(Od + row1 * 132 + nf * 8 + 2 * c4) = hi;
            }
            if (c4 == 0) {
                Ld[row0] = l_lo[rb];
                Ld[row1] = l_hi[rb];
            }
        }
    }
    __syncthreads();
    if (khalf == 0) {
#pragma unroll
        for (int rb = 0; rb < 2; ++rb) {
            int row0 = qgroup * 32 + rb * 16 + r4;
            int row1 = row0 + 8;
            float invlo = 1.f / (l_lo[rb] + Ld[row0]);
            float invhi = 1.f / (l_hi[rb] + Ld[row1]);
            float* outlo = CTX + ((size_t)b * N_ + q0 + row0) * CK;
            float* outhi = CTX + ((size_t)b * N_ + q0 + row1) * CK;
#pragma unroll
            for (int nf = 0; nf < 16; ++nf) {
                float2 plo = *(const float2*)(Od + row0 * 132 + nf * 8 + 2 * c4);
                float2 phi = *(const float2*)(Od + row1 * 132 + nf * 8 + 2 * c4);
                float2 lo, hi;
                lo.x = (accO[rb][nf][0] + plo.x) * invlo;
                lo.y = (accO[rb][nf][1] + plo.y) * invlo;
                hi.x = (accO[rb][nf][2] + phi.x) * invhi;
                hi.y = (accO[rb][nf][3] + phi.y) * invhi;
                *(float2*)(outlo + nf * 8 + 2 * c4) = lo;
                *(float2*)(outhi + nf * 8 + 2 * c4) = hi;
            }
        }
    }
}

// ---------------- launch ----------------
extern "C" void kernel_launch(void* const* d_in, const int* in_sizes, int n_in,
                              void* d_out, int out_size) {
    const float* x_enc = (const float*)d_in[0];
    const float* x_dec = (const float*)d_in[1];
    const float* wk    = (const float*)d_in[2];
    const float* bk    = (const float*)d_in[3];
    const float* gk    = (const float*)d_in[4];
    const float* betak = (const float*)d_in[5];
    const float* mk    = (const float*)d_in[6];
    const float* vk    = (const float*)d_in[7];
    const float* wq    = (const float*)d_in[8];
    const float* bq    = (const float*)d_in[9];
    const float* gq    = (const float*)d_in[10];
    const float* betaq = (const float*)d_in[11];
    const float* mq    = (const float*)d_in[12];
    const float* vq    = (const float*)d_in[13];
    const float* wv    = (const float*)d_in[14];
    const float* bv    = (const float*)d_in[15];
    const float* wo    = (const float*)d_in[16];
    const float* bo    = (const float*)d_in[17];
    float* out = (float*)d_out;

    float *pq, *pk, *pv, *pctx, *pwq, *pwk, *pbq, *pbk;
    cudaGetSymbolAddress((void**)&pq, g_q);
    cudaGetSymbolAddress((void**)&pk, g_k);
    cudaGetSymbolAddress((void**)&pv, g_v);
    cudaGetSymbolAddress((void**)&pctx, g_ctx);
    cudaGetSymbolAddress((void**)&pwq, g_wq);
    cudaGetSymbolAddress((void**)&pwk, g_wk);
    cudaGetSymbolAddress((void**)&pbq, g_bq);
    cudaGetSymbolAddress((void**)&pbk, g_bk);

    prep_kernel<<<(CK * CIN + 255) / 256, 256>>>(wk, bk, gk, betak, mk, vk,
                                                 wq, bq, gq, betaq, mq, vq);

    cudaFuncSetAttribute(gemm_tc_proj3, cudaFuncAttributeMaxDynamicSharedMemorySize, PJ_SMEM);
    cudaFuncSetAttribute(gemm_tc_out, cudaFuncAttributeMaxDynamicSharedMemorySize, GO_SMEM);
    cudaFuncSetAttribute(flash_mma, cudaFuncAttributeMaxDynamicSharedMemorySize, SMEM_FLASH);

    gemm_tc_proj3<<<dim3(N_ / 128, 3, B_), 256, PJ_SMEM>>>(
        x_dec, x_enc, pwq, pwk, wv, pbq, pbk, bv, pq, pk, pv);

    flash_mma<<<dim3(N_ / 128, B_), 256, SMEM_FLASH>>>(pq, pk, pv, pctx);

    gemm_tc_out<<<dim3(N_ / 128, COUT / 128, B_), 256, GO_SMEM>>>(pctx, wo, bo, out);
}

// round 8
// speedup vs baseline: 1.2804x; 1.0690x over previous
#include <cuda_runtime.h>
#include <cstdint>

#define B_   4
#define N_   4096
#define CIN  256
#define CK   128
#define COUT 256

// ---------------- scratch (no allocs allowed) ----------------
__device__ float g_q[B_ * N_ * CK];    // [b][n][128]
__device__ float g_k[B_ * N_ * CK];    // [b][n][128]
__device__ float g_v[B_ * N_ * CK];    // [b][n][128]
__device__ float g_ctx[B_ * N_ * CK];  // [b][n][128]
__device__ float g_wq[CK * CIN];
__device__ float g_wk[CK * CIN];
__device__ float g_bq[CK];
__device__ float g_bk[CK];

// ================= helpers =================
__device__ __forceinline__ uint32_t f2tf32(float f) {
    uint32_t u;
    asm("cvt.rna.tf32.f32 %0, %1;" : "=r"(u) : "f"(f));
    return u;
}
__device__ __forceinline__ void mma_tf32(float* d, uint32_t a0, uint32_t a1,
                                         uint32_t a2, uint32_t a3,
                                         uint32_t b0, uint32_t b1) {
    asm volatile(
        "mma.sync.aligned.m16n8k8.row.col.f32.tf32.tf32.f32 "
        "{%0,%1,%2,%3}, {%4,%5,%6,%7}, {%8,%9}, {%0,%1,%2,%3};"
        : "+f"(d[0]), "+f"(d[1]), "+f"(d[2]), "+f"(d[3])
        : "r"(a0), "r"(a1), "r"(a2), "r"(a3), "r"(b0), "r"(b1));
}

// ---------------- BN folding ----------------
__global__ void prep_kernel(const float* __restrict__ wk, const float* __restrict__ bk,
                            const float* __restrict__ gk, const float* __restrict__ betak,
                            const float* __restrict__ mk, const float* __restrict__ vk,
                            const float* __restrict__ wq, const float* __restrict__ bq,
                            const float* __restrict__ gq, const float* __restrict__ betaq,
                            const float* __restrict__ mq, const float* __restrict__ vq) {
    int idx = blockIdx.x * blockDim.x + threadIdx.x;
    if (idx >= CK * CIN) return;
    int o = idx / CIN;
    float sk = gk[o] * rsqrtf(vk[o] + 1e-5f);
    float sq = gq[o] * rsqrtf(vq[o] + 1e-5f);
    g_wk[idx] = wk[idx] * sk;
    g_wq[idx] = wq[idx] * sq;
    if ((idx % CIN) == 0) {
        g_bk[o] = (bk[o] - mk[o]) * sk + betak[o];
        g_bq[o] = (bq[o] - mq[o]) * sq + betaq[o];
    }
}

// ======== fused 3-way projection GEMM (stage A, 2 CTAs/SM, conflict-free APAD) ========
#define PJ_APAD 136
#define PJ_BPAD 72
#define PJ_SMEM ((64 * PJ_APAD + 128 * PJ_BPAD) * 4)

__global__ __launch_bounds__(256, 2) void gemm_tc_proj3(
    const float* __restrict__ xdec, const float* __restrict__ xenc,
    const float* __restrict__ wq, const float* __restrict__ wk,
    const float* __restrict__ wv,
    const float* __restrict__ bq, const float* __restrict__ bk,
    const float* __restrict__ bv,
    float* __restrict__ yq, float* __restrict__ yk, float* __restrict__ yv) {
    extern __shared__ uint32_t dsm[];
    uint32_t* As = dsm;                 // [64 c][136 n] tf32
    uint32_t* Bs = dsm + 64 * PJ_APAD;  // [128 o][72 interleaved c] tf32

    int which = blockIdx.y;
    const float* X = (which == 0) ? xdec : xenc;
    const float* W = (which == 0) ? wq : (which == 1) ? wk : wv;
    const float* bias = (which == 0) ? bq : (which == 1) ? bk : bv;
    float* Y = (which == 0) ? yq : (which == 1) ? yk : yv;
    int relu = (which < 2);

    int b = blockIdx.z;
    int n0 = blockIdx.x * 128;
    const float* Xb = X + (size_t)b * CIN * N_;
    float* Yb = Y + (size_t)b * (size_t)N_ * CK;

    int tid = threadIdx.x;
    int w = tid >> 5, lane = tid & 31;
    int r4 = lane >> 2, c4 = lane & 3;

    float accD[16][4];
#pragma unroll
    for (int i = 0; i < 16; ++i)
#pragma unroll
        for (int j = 0; j < 4; ++j) accD[i][j] = 0.f;

    float4 ra[8];
#pragma unroll
    for (int i = 0; i < 8; ++i) {
        int idx = tid + i * 256;
        int cc = idx >> 5, nq = idx & 31;
        ra[i] = *(const float4*)(Xb + (size_t)cc * N_ + n0 + nq * 4);
    }

    for (int c0 = 0; c0 < CIN; c0 += 64) {
        __syncthreads();
#pragma unroll
        for (int i = 0; i < 8; ++i) {
            int idx = tid + i * 256;
            int cc = idx >> 5, nq = idx & 31;
            uint4 u;
            u.x = f2tf32(ra[i].x); u.y = f2tf32(ra[i].y);
            u.z = f2tf32(ra[i].z); u.w = f2tf32(ra[i].w);
            *(uint4*)(As + cc * PJ_APAD + nq * 4) = u;
        }
#pragma unroll
        for (int i = 0; i < 8; ++i) {
            int idx = tid + i * 256;
            int oo = idx >> 4, cq = idx & 15;
            float4 v = *(const float4*)(W + (size_t)oo * CIN + c0 + cq * 4);
            uint32_t* dst = Bs + oo * PJ_BPAD + (cq >> 1) * 8 + (cq & 1);
            dst[0] = f2tf32(v.x); dst[2] = f2tf32(v.y);
            dst[4] = f2tf32(v.z); dst[6] = f2tf32(v.w);
        }
        __syncthreads();

        if (c0 + 64 < CIN) {
#pragma unroll
            for (int i = 0; i < 8; ++i) {
                int idx = tid + i * 256;
                int cc = idx >> 5, nq = idx & 31;
                ra[i] = *(const float4*)(Xb + (size_t)(c0 + 64 + cc) * N_ + n0 + nq * 4);
            }
        }

#pragma unroll
        for (int kk = 0; kk < 8; ++kk) {
            uint32_t a0 = As[(kk * 8 + c4) * PJ_APAD + w * 16 + r4];
            uint32_t a1 = As[(kk * 8 + c4) * PJ_APAD + w * 16 + r4 + 8];
            uint32_t a2 = As[(kk * 8 + c4 + 4) * PJ_APAD + w * 16 + r4];
            uint32_t a3 = As[(kk * 8 + c4 + 4) * PJ_APAD + w * 16 + r4 + 8];
#pragma unroll
            for (int nf = 0; nf < 16; ++nf) {
                uint2 bf = *(const uint2*)(Bs + (nf * 8 + r4) * PJ_BPAD + kk * 8 + 2 * c4);
                mma_tf32(accD[nf], a0, a1, a2, a3, bf.x, bf.y);
            }
        }
    }

    int nlo = n0 + w * 16 + r4;
#pragma unroll
    for (int nf = 0; nf < 16; ++nf) {
        int o = nf * 8 + 2 * c4;
        float b0 = __ldg(bias + o), b1 = __ldg(bias + o + 1);
        float2 lo, hi;
        lo.x = accD[nf][0] + b0; lo.y = accD[nf][1] + b1;
        hi.x = accD[nf][2] + b0; hi.y = accD[nf][3] + b1;
        if (relu) {
            lo.x = fmaxf(lo.x, 0.f); lo.y = fmaxf(lo.y, 0.f);
            hi.x = fmaxf(hi.x, 0.f); hi.y = fmaxf(hi.y, 0.f);
        }
        *(float2*)(Yb + (size_t)nlo * CK + o) = lo;
        *(float2*)(Yb + (size_t)(nlo + 8) * CK + o) = hi;
    }
}

// ======== tensor-core output GEMM (stage both operands) ========
#define GO_PAD 72
#define GO_SMEM ((128 * GO_PAD * 2) * 4)

__global__ __launch_bounds__(256) void gemm_tc_out(
    const float* __restrict__ CTX, const float* __restrict__ WO,
    const float* __restrict__ bo, float* __restrict__ Y) {
    extern __shared__ uint32_t dsm[];
    uint32_t* As = dsm;                // [128 o][72] WO
    uint32_t* Bs = dsm + 128 * GO_PAD; // [128 n][72] CTX

    int b = blockIdx.z;
    int n0 = blockIdx.x * 128, o0 = blockIdx.y * 128;
    const float* Cb = CTX + (size_t)b * N_ * CK;
    float* Yb = Y + (size_t)b * (size_t)COUT * N_;

    int tid = threadIdx.x;
    int w = tid >> 5, lane = tid & 31;
    int r4 = lane >> 2, c4 = lane & 3;

    float accD[16][4];
#pragma unroll
    for (int i = 0; i < 16; ++i)
#pragma unroll
        for (int j = 0; j < 4; ++j) accD[i][j] = 0.f;

    float4 ra[8], rb[8];
#pragma unroll
    for (int i = 0; i < 8; ++i) {
        int idx = tid + i * 256;
        int oo = idx >> 4, cq = idx & 15;
        ra[i] = *(const float4*)(WO + (size_t)(o0 + oo) * CK + cq * 4);
        rb[i] = *(const float4*)(Cb + (size_t)(n0 + oo) * CK + cq * 4);
    }

    for (int c0 = 0; c0 < CK; c0 += 64) {
        __syncthreads();
#pragma unroll
        for (int i = 0; i < 8; ++i) {
            int idx = tid + i * 256;
            int oo = idx >> 4, cq = idx & 15;
            uint32_t* dsta = As + oo * GO_PAD + (cq >> 1) * 8 + (cq & 1);
            dsta[0] = f2tf32(ra[i].x); dsta[2] = f2tf32(ra[i].y);
            dsta[4] = f2tf32(ra[i].z); dsta[6] = f2tf32(ra[i].w);
            uint32_t* dstb = Bs + oo * GO_PAD + (cq >> 1) * 8 + (cq & 1);
            dstb[0] = f2tf32(rb[i].x); dstb[2] = f2tf32(rb[i].y);
            dstb[4] = f2tf32(rb[i].z); dstb[6] = f2tf32(rb[i].w);
        }
        __syncthreads();

        if (c0 + 64 < CK) {
#pragma unroll
            for (int i = 0; i < 8; ++i) {
                int idx = tid + i * 256;
                int oo = idx >> 4, cq = idx & 15;
                ra[i] = *(const float4*)(WO + (size_t)(o0 + oo) * CK + c0 + 64 + cq * 4);
                rb[i] = *(const float4*)(Cb + (size_t)(n0 + oo) * CK + c0 + 64 + cq * 4);
            }
        }

#pragma unroll
        for (int kk = 0; kk < 8; ++kk) {
            uint2 a02 = *(const uint2*)(As + (w * 16 + r4) * GO_PAD + kk * 8 + 2 * c4);
            uint2 a13 = *(const uint2*)(As + (w * 16 + r4 + 8) * GO_PAD + kk * 8 + 2 * c4);
#pragma unroll
            for (int nf = 0; nf < 16; ++nf) {
                uint2 bf = *(const uint2*)(Bs + (nf * 8 + r4) * GO_PAD + kk * 8 + 2 * c4);
                mma_tf32(accD[nf], a02.x, a13.x, a02.y, a13.y, bf.x, bf.y);
            }
        }
    }

    int olo = o0 + w * 16 + r4;
    float blo = __ldg(bo + olo), bhi = __ldg(bo + olo + 8);
#pragma unroll
    for (int nf = 0; nf < 16; ++nf) {
        int n = n0 + nf * 8 + 2 * c4;
        float2 lo, hi;
        lo.x = accD[nf][0] + blo; lo.y = accD[nf][1] + blo;
        hi.x = accD[nf][2] + bhi; hi.y = accD[nf][3] + bhi;
        *(float2*)(Yb + (size_t)olo * N_ + n) = lo;
        *(float2*)(Yb + (size_t)(olo + 8) * N_ + n) = hi;
    }
}

// ---------------- flash attention: key-split 8-warp + double-buffered K ----------------
// Warp w: qgroup=w&3 (32 query rows), khalf=w>>2 (32 of 64 keys/tile).
// K double-buffered in smem; V register-staged. Loads issue under MMA cover;
// 2 barriers/tile, no exposed load phase.
#define QPAD 132
#define KPAD 132
#define VPAD 136
#define PPAD 68
#define KBUF (64 * KPAD)
#define OFF_K (128 * QPAD)
#define OFF_V (OFF_K + 2 * KBUF)
#define OFF_P (OFF_V + 64 * VPAD)
#define SMEM_FLASH ((OFF_P + 128 * PPAD) * 4)

__global__ __launch_bounds__(256, 1) void flash_mma(
    const float* __restrict__ Q, const float* __restrict__ K,
    const float* __restrict__ V, float* __restrict__ CTX) {
    extern __shared__ uint32_t sm[];
    uint32_t* Qs = sm;
    uint32_t* Ks = sm + OFF_K;   // two buffers of KBUF
    uint32_t* Vs = sm + OFF_V;
    uint32_t* Ps = sm + OFF_P;

    int tid = threadIdx.x;
    int w = tid >> 5, lane = tid & 31;
    int qgroup = w & 3, khalf = w >> 2;
    int r4 = lane >> 2, c4 = lane & 3;
    int b = blockIdx.y;
    int q0 = blockIdx.x * 128;
    const float4* Qg = (const float4*)(Q + ((size_t)b * N_ + q0) * CK);
    const float* Kb = K + (size_t)b * N_ * CK;
    const float* Vb = V + (size_t)b * N_ * CK;

    // prologue: Q (scale + tf32) and K(0) into buffer 0
    {
        const float sc = 0.08838834764831845f;  // 1/sqrt(128)
        for (int idx = tid; idx < 128 * 32; idx += 256) {
            int r = idx >> 5, c = idx & 31;
            float4 v = Qg[idx];
            uint32_t* dst = Qs + r * QPAD + c * 4;
            dst[0] = f2tf32(v.x * sc);
            dst[1] = f2tf32(v.y * sc);
            dst[2] = f2tf32(v.z * sc);
            dst[3] = f2tf32(v.w * sc);
        }
        const float4* Kg = (const float4*)Kb;
#pragma unroll
        for (int i = 0; i < 8; ++i) {
            int idx = tid + i * 256;
            int r = idx >> 5, c = idx & 31;
            float4 kv = Kg[idx];
            uint32_t* kd = Ks + r * KPAD + c * 4;
            kd[0] = f2tf32(kv.x); kd[1] = f2tf32(kv.y);
            kd[2] = f2tf32(kv.z); kd[3] = f2tf32(kv.w);
        }
    }
    __syncthreads();

    float accO[2][16][4];
#pragma unroll
    for (int rb = 0; rb < 2; ++rb)
#pragma unroll
        for (int i = 0; i < 16; ++i)
#pragma unroll
            for (int j = 0; j < 4; ++j) accO[rb][i][j] = 0.f;
    float l_lo[2] = {0.f, 0.f}, l_hi[2] = {0.f, 0.f};

    const uint32_t* qbase = Qs + (qgroup * 32) * QPAD;
    uint32_t* pbase = Ps + (qgroup * 32) * PPAD;
    const int kcol = khalf * 32;

    const int NT = N_ / 64;
    for (int t = 0; t < NT; ++t) {
        const uint32_t* Kcur = Ks + (t & 1) * KBUF;
        uint32_t* Knxt = Ks + ((t + 1) & 1) * KBUF;

        // stage V(t) in registers; S-compute below covers the LDG latency
        float4 vr[8];
        {
            const float4* Vg = (const float4*)(Vb + (size_t)(t * 64) * CK);
#pragma unroll
            for (int i = 0; i < 8; ++i) vr[i] = Vg[tid + i * 256];
        }

        // S = Q . K^T over this warp's 32 keys (16 k-steps, 4 n-frags, 2 rowblocks)
        float accS[2][4][4];
#pragma unroll
        for (int rb = 0; rb < 2; ++rb)
#pragma unroll
            for (int i = 0; i < 4; ++i)
#pragma unroll
                for (int j = 0; j < 4; ++j) accS[rb][i][j] = 0.f;
#pragma unroll
        for (int kk = 0; kk < 16; ++kk) {
            uint32_t a[2][4];
#pragma unroll
            for (int rb = 0; rb < 2; ++rb) {
                const uint32_t* qb = qbase + (rb * 16) * QPAD;
                a[rb][0] = qb[r4 * QPAD + kk * 8 + c4];
                a[rb][1] = qb[(r4 + 8) * QPAD + kk * 8 + c4];
                a[rb][2] = qb[r4 * QPAD + kk * 8 + c4 + 4];
                a[rb][3] = qb[(r4 + 8) * QPAD + kk * 8 + c4 + 4];
            }
#pragma unroll
            for (int nf = 0; nf < 4; ++nf) {
                uint32_t b0 = Kcur[(kcol + nf * 8 + r4) * KPAD + kk * 8 + c4];
                uint32_t b1 = Kcur[(kcol + nf * 8 + r4) * KPAD + kk * 8 + c4 + 4];
                mma_tf32(accS[0][nf], a[0][0], a[0][1], a[0][2], a[0][3], b0, b1);
                mma_tf32(accS[1][nf], a[1][0], a[1][1], a[1][2], a[1][3], b0, b1);
            }
        }

        // P = exp(S - 4) into warp-private region
#pragma unroll
        for (int rb = 0; rb < 2; ++rb) {
            uint32_t* pb = pbase + (rb * 16) * PPAD;
            float slo = 0.f, shi = 0.f;
#pragma unroll
            for (int nf = 0; nf < 4; ++nf) {
                float p0 = __expf(accS[rb][nf][0] - 4.f);
                float p1 = __expf(accS[rb][nf][1] - 4.f);
                float p2 = __expf(accS[rb][nf][2] - 4.f);
                float p3 = __expf(accS[rb][nf][3] - 4.f);
                slo += p0 + p1;
                shi += p2 + p3;
                uint2 lo; lo.x = f2tf32(p0); lo.y = f2tf32(p1);
                uint2 hi; hi.x = f2tf32(p2); hi.y = f2tf32(p3);
                *(uint2*)(pb + r4 * PPAD + kcol + nf * 8 + 2 * c4) = lo;
                *(uint2*)(pb + (r4 + 8) * PPAD + kcol + nf * 8 + 2 * c4) = hi;
            }
            slo += __shfl_xor_sync(0xffffffffu, slo, 1);
            slo += __shfl_xor_sync(0xffffffffu, slo, 2);
            shi += __shfl_xor_sync(0xffffffffu, shi, 1);
            shi += __shfl_xor_sync(0xffffffffu, shi, 2);
            l_lo[rb] += slo;
            l_hi[rb] += shi;
        }
        __syncwarp();

        // stage K(t+1) in registers (PV below covers latency)
        float4 kr[8];
        bool more = (t + 1 < NT);
        if (more) {
            const float4* Kg = (const float4*)(Kb + (size_t)((t + 1) * 64) * CK);
#pragma unroll
            for (int i = 0; i < 8; ++i) kr[i] = Kg[tid + i * 256];
        }

        // commit V(t) to smem (prev tile's Vs readers all pre-B2 of t-1)
#pragma unroll
        for (int i = 0; i < 8; ++i) {
            int idx = tid + i * 256;
            int r = idx >> 5, c = idx & 31;
            uint32_t* vd = Vs + r * VPAD + c * 4;
            vd[0] = f2tf32(vr[i].x); vd[1] = f2tf32(vr[i].y);
            vd[2] = f2tf32(vr[i].z); vd[3] = f2tf32(vr[i].w);
        }
        __syncthreads();  // B1: Vs complete; all S reads of Kcur done

        // O += P . V over this warp's 32 keys
#pragma unroll
        for (int kk = 0; kk < 4; ++kk) {
            uint32_t a[2][4];
#pragma unroll
            for (int rb = 0; rb < 2; ++rb) {
                const uint32_t* pb = pbase + (rb * 16) * PPAD;
                a[rb][0] = pb[r4 * PPAD + kcol + kk * 8 + c4];
                a[rb][1] = pb[(r4 + 8) * PPAD + kcol + kk * 8 + c4];
                a[rb][2] = pb[r4 * PPAD + kcol + kk * 8 + c4 + 4];
                a[rb][3] = pb[(r4 + 8) * PPAD + kcol + kk * 8 + c4 + 4];
            }
#pragma unroll
            for (int nf = 0; nf < 16; ++nf) {
                uint32_t b0 = Vs[(kcol + kk * 8 + c4) * VPAD + nf * 8 + r4];
                uint32_t b1 = Vs[(kcol + kk * 8 + c4 + 4) * VPAD + nf * 8 + r4];
                mma_tf32(accO[0][nf], a[0][0], a[0][1], a[0][2], a[0][3], b0, b1);
                mma_tf32(accO[1][nf], a[1][0], a[1][1], a[1][2], a[1][3], b0, b1);
            }
        }

        // commit K(t+1) into the other buffer (its readers come after B2)
        if (more) {
#pragma unroll
            for (int i = 0; i < 8; ++i) {
                int idx = tid + i * 256;
                int r = idx >> 5, c = idx & 31;
                uint32_t* kd = Knxt + r * KPAD + c * 4;
                kd[0] = f2tf32(kr[i].x); kd[1] = f2tf32(kr[i].y);
                kd[2] = f2tf32(kr[i].z); kd[3] = f2tf32(kr[i].w);
            }
        }
        __syncthreads();  // B2: Knxt complete; all PV reads of Vs done
    }

    // ---- merge key-halves ----
    float* Od = (float*)Qs;  // [128][132] partial O from khalf=1
    float* Ld = (float*)Ks;  // [128] partial l from khalf=1
    if (khalf == 1) {
#pragma unroll
        for (int rb = 0; rb < 2; ++rb) {
            int row0 = qgroup * 32 + rb * 16 + r4;
            int row1 = row0 + 8;
#pragma unroll
            for (int nf = 0; nf < 16; ++nf) {
                float2 lo; lo.x = accO[rb][nf][0]; lo.y = accO[rb][nf][1];
                float2 hi; hi.x = accO[rb][nf][2]; hi.y = accO[rb][nf][3];
                *(float2*)(Od + row0 * 132 + nf * 8 + 2 * c4) = lo;
                *(float2*)(Od + row1 * 132 + nf * 8 + 2 * c4) = hi;
            }
            if (c4 == 0) {
                Ld[row0] = l_lo[rb];
                Ld[row1] = l_hi[rb];
            }
        }
    }
    __syncthreads();
    if (khalf == 0) {
#pragma unroll
        for (int rb = 0; rb < 2; ++rb) {
            int row0 = qgroup * 32 + rb * 16 + r4;
            int row1 = row0 + 8;
            float invlo = 1.f / (l_lo[rb] + Ld[row0]);
            float invhi = 1.f / (l_hi[rb] + Ld[row1]);
            float* outlo = CTX + ((size_t)b * N_ + q0 + row0) * CK;
            float* outhi = CTX + ((size_t)b * N_ + q0 + row1) * CK;
#pragma unroll
            for (int nf = 0; nf < 16; ++nf) {
                float2 plo = *(const float2*)(Od + row0 * 132 + nf * 8 + 2 * c4);
                float2 phi = *(const float2*)(Od + row1 * 132 + nf * 8 + 2 * c4);
                float2 lo, hi;
                lo.x = (accO[rb][nf][0] + plo.x) * invlo;
                lo.y = (accO[rb][nf][1] + plo.y) * invlo;
                hi.x = (accO[rb][nf][2] + phi.x) * invhi;
                hi.y = (accO[rb][nf][3] + phi.y) * invhi;
                *(float2*)(outlo + nf * 8 + 2 * c4) = lo;
                *(float2*)(outhi + nf * 8 + 2 * c4) = hi;
            }
        }
    }
}

// ---------------- launch ----------------
extern "C" void kernel_launch(void* const* d_in, const int* in_sizes, int n_in,
                              void* d_out, int out_size) {
    const float* x_enc = (const float*)d_in[0];
    const float* x_dec = (const float*)d_in[1];
    const float* wk    = (const float*)d_in[2];
    const float* bk    = (const float*)d_in[3];
    const float* gk    = (const float*)d_in[4];
    const float* betak = (const float*)d_in[5];
    const float* mk    = (const float*)d_in[6];
    const float* vk    = (const float*)d_in[7];
    const float* wq    = (const float*)d_in[8];
    const float* bq    = (const float*)d_in[9];
    const float* gq    = (const float*)d_in[10];
    const float* betaq = (const float*)d_in[11];
    const float* mq    = (const float*)d_in[12];
    const float* vq    = (const float*)d_in[13];
    const float* wv    = (const float*)d_in[14];
    const float* bv    = (const float*)d_in[15];
    const float* wo    = (const float*)d_in[16];
    const float* bo    = (const float*)d_in[17];
    float* out = (float*)d_out;

    float *pq, *pk, *pv, *pctx, *pwq, *pwk, *pbq, *pbk;
    cudaGetSymbolAddress((void**)&pq, g_q);
    cudaGetSymbolAddress((void**)&pk, g_k);
    cudaGetSymbolAddress((void**)&pv, g_v);
    cudaGetSymbolAddress((void**)&pctx, g_ctx);
    cudaGetSymbolAddress((void**)&pwq, g_wq);
    cudaGetSymbolAddress((void**)&pwk, g_wk);
    cudaGetSymbolAddress((void**)&pbq, g_bq);
    cudaGetSymbolAddress((void**)&pbk, g_bk);

    prep_kernel<<<(CK * CIN + 255) / 256, 256>>>(wk, bk, gk, betak, mk, vk,
                                                 wq, bq, gq, betaq, mq, vq);

    cudaFuncSetAttribute(gemm_tc_proj3, cudaFuncAttributeMaxDynamicSharedMemorySize, PJ_SMEM);
    cudaFuncSetAttribute(gemm_tc_out, cudaFuncAttributeMaxDynamicSharedMemorySize, GO_SMEM);
    cudaFuncSetAttribute(flash_mma, cudaFuncAttributeMaxDynamicSharedMemorySize, SMEM_FLASH);

    gemm_tc_proj3<<<dim3(N_ / 128, 3, B_), 256, PJ_SMEM>>>(
        x_dec, x_enc, pwq, pwk, wv, pbq, pbk, bv, pq, pk, pv);

    flash_mma<<<dim3(N_ / 128, B_), 256, SMEM_FLASH>>>(pq, pk, pv, pctx);

    gemm_tc_out<<<dim3(N_ / 128, COUT / 128, B_), 256, GO_SMEM>>>(pctx, wo, bo, out);
}

// round 9
// speedup vs baseline: 2.3362x; 1.8246x over previous
#include <cuda_runtime.h>
#include <cuda_fp16.h>
#include <cstdint>

#define B_   4
#define N_   4096
#define CIN  256
#define CK   128
#define COUT 256

// ---------------- scratch (no allocs allowed) ----------------
__device__ __half g_qh[B_ * N_ * CK];   // [b][n][128] fp16, pre-scaled by 1/sqrt(128)
__device__ __half g_kh[B_ * N_ * CK];   // [b][n][128] fp16
__device__ float  g_v[B_ * N_ * CK];    // [b][n][128] fp32 (transpose input)
__device__ __half g_vth[B_ * CK * N_];  // [b][d][n] fp16 (transposed V)
__device__ float  g_ctx[B_ * N_ * CK];  // [b][n][128]
__device__ float  g_wq[CK * CIN];
__device__ float  g_wk[CK * CIN];
__device__ float  g_bq[CK];
__device__ float  g_bk[CK];

// ================= helpers =================
__device__ __forceinline__ uint32_t f2tf32(float f) {
    uint32_t u;
    asm("cvt.rna.tf32.f32 %0, %1;" : "=r"(u) : "f"(f));
    return u;
}
__device__ __forceinline__ uint32_t pack_h2(float lo, float hi) {
    __half2 h = __floats2half2_rn(lo, hi);
    return *(uint32_t*)&h;
}
__device__ __forceinline__ void mma_tf32(float* d, uint32_t a0, uint32_t a1,
                                         uint32_t a2, uint32_t a3,
                                         uint32_t b0, uint32_t b1) {
    asm volatile(
        "mma.sync.aligned.m16n8k8.row.col.f32.tf32.tf32.f32 "
        "{%0,%1,%2,%3}, {%4,%5,%6,%7}, {%8,%9}, {%0,%1,%2,%3};"
        : "+f"(d[0]), "+f"(d[1]), "+f"(d[2]), "+f"(d[3])
        : "r"(a0), "r"(a1), "r"(a2), "r"(a3), "r"(b0), "r"(b1));
}
__device__ __forceinline__ void mma_f16(float* d, uint32_t a0, uint32_t a1,
                                        uint32_t a2, uint32_t a3,
                                        uint32_t b0, uint32_t b1) {
    asm volatile(
        "mma.sync.aligned.m16n8k16.row.col.f32.f16.f16.f32 "
        "{%0,%1,%2,%3}, {%4,%5,%6,%7}, {%8,%9}, {%0,%1,%2,%3};"
        : "+f"(d[0]), "+f"(d[1]), "+f"(d[2]), "+f"(d[3])
        : "r"(a0), "r"(a1), "r"(a2), "r"(a3), "r"(b0), "r"(b1));
}

// ---------------- BN folding ----------------
__global__ void prep_kernel(const float* __restrict__ wk, const float* __restrict__ bk,
                            const float* __restrict__ gk, const float* __restrict__ betak,
                            const float* __restrict__ mk, const float* __restrict__ vk,
                            const float* __restrict__ wq, const float* __restrict__ bq,
                            const float* __restrict__ gq, const float* __restrict__ betaq,
                            const float* __restrict__ mq, const float* __restrict__ vq) {
    int idx = blockIdx.x * blockDim.x + threadIdx.x;
    if (idx >= CK * CIN) return;
    int o = idx / CIN;
    float sk = gk[o] * rsqrtf(vk[o] + 1e-5f);
    float sq = gq[o] * rsqrtf(vq[o] + 1e-5f);
    g_wk[idx] = wk[idx] * sk;
    g_wq[idx] = wq[idx] * sq;
    if ((idx % CIN) == 0) {
        g_bk[o] = (bk[o] - mk[o]) * sk + betak[o];
        g_bq[o] = (bq[o] - mq[o]) * sq + betaq[o];
    }
}

// ---------------- V transpose: [b][n][128] fp32 -> [b][128][n] fp16 ----------------
__global__ __launch_bounds__(256) void transpose_v(const float* __restrict__ V,
                                                   __half* __restrict__ Vt) {
    __shared__ float tile[32][33];
    int b = blockIdx.z;
    int n0 = blockIdx.x * 32, d0 = blockIdx.y * 32;
    const float* Vb = V + (size_t)b * N_ * CK;
    __half* Tb = Vt + (size_t)b * CK * N_;
    int tx = threadIdx.x, ty = threadIdx.y;  // 32 x 8
#pragma unroll
    for (int i = 0; i < 32; i += 8)
        tile[ty + i][tx] = Vb[(size_t)(n0 + ty + i) * CK + d0 + tx];
    __syncthreads();
#pragma unroll
    for (int i = 0; i < 32; i += 8)
        Tb[(size_t)(d0 + ty + i) * N_ + n0 + tx] = __float2half(tile[tx][ty + i]);
}

// ======== fused 3-way projection GEMM (tf32 mma; Q/K epilogues emit fp16) ========
#define PJ_APAD 136
#define PJ_BPAD 72
#define PJ_SMEM ((64 * PJ_APAD + 128 * PJ_BPAD) * 4)

__global__ __launch_bounds__(256, 2) void gemm_tc_proj3(
    const float* __restrict__ xdec, const float* __restrict__ xenc,
    const float* __restrict__ wq, const float* __restrict__ wk,
    const float* __restrict__ wv,
    const float* __restrict__ bq, const float* __restrict__ bk,
    const float* __restrict__ bv,
    __half* __restrict__ yqh, __half* __restrict__ ykh, float* __restrict__ yv) {
    extern __shared__ uint32_t dsm[];
    uint32_t* As = dsm;                 // [64 c][136 n] tf32
    uint32_t* Bs = dsm + 64 * PJ_APAD;  // [128 o][72 interleaved c] tf32

    int which = blockIdx.y;
    const float* X = (which == 0) ? xdec : xenc;
    const float* W = (which == 0) ? wq : (which == 1) ? wk : wv;
    const float* bias = (which == 0) ? bq : (which == 1) ? bk : bv;

    int b = blockIdx.z;
    int n0 = blockIdx.x * 128;
    const float* Xb = X + (size_t)b * CIN * N_;

    int tid = threadIdx.x;
    int w = tid >> 5, lane = tid & 31;
    int r4 = lane >> 2, c4 = lane & 3;

    float accD[16][4];
#pragma unroll
    for (int i = 0; i < 16; ++i)
#pragma unroll
        for (int j = 0; j < 4; ++j) accD[i][j] = 0.f;

    float4 ra[8];
#pragma unroll
    for (int i = 0; i < 8; ++i) {
        int idx = tid + i * 256;
        int cc = idx >> 5, nq = idx & 31;
        ra[i] = *(const float4*)(Xb + (size_t)cc * N_ + n0 + nq * 4);
    }

    for (int c0 = 0; c0 < CIN; c0 += 64) {
        __syncthreads();
#pragma unroll
        for (int i = 0; i < 8; ++i) {
            int idx = tid + i * 256;
            int cc = idx >> 5, nq = idx & 31;
            uint4 u;
            u.x = f2tf32(ra[i].x); u.y = f2tf32(ra[i].y);
            u.z = f2tf32(ra[i].z); u.w = f2tf32(ra[i].w);
            *(uint4*)(As + cc * PJ_APAD + nq * 4) = u;
        }
#pragma unroll
        for (int i = 0; i < 8; ++i) {
            int idx = tid + i * 256;
            int oo = idx >> 4, cq = idx & 15;
            float4 v = *(const float4*)(W + (size_t)oo * CIN + c0 + cq * 4);
            uint32_t* dst = Bs + oo * PJ_BPAD + (cq >> 1) * 8 + (cq & 1);
            dst[0] = f2tf32(v.x); dst[2] = f2tf32(v.y);
            dst[4] = f2tf32(v.z); dst[6] = f2tf32(v.w);
        }
        __syncthreads();

        if (c0 + 64 < CIN) {
#pragma unroll
            for (int i = 0; i < 8; ++i) {
                int idx = tid + i * 256;
                int cc = idx >> 5, nq = idx & 31;
                ra[i] = *(const float4*)(Xb + (size_t)(c0 + 64 + cc) * N_ + n0 + nq * 4);
            }
        }

#pragma unroll
        for (int kk = 0; kk < 8; ++kk) {
            uint32_t a0 = As[(kk * 8 + c4) * PJ_APAD + w * 16 + r4];
            uint32_t a1 = As[(kk * 8 + c4) * PJ_APAD + w * 16 + r4 + 8];
            uint32_t a2 = As[(kk * 8 + c4 + 4) * PJ_APAD + w * 16 + r4];
            uint32_t a3 = As[(kk * 8 + c4 + 4) * PJ_APAD + w * 16 + r4 + 8];
#pragma unroll
            for (int nf = 0; nf < 16; ++nf) {
                uint2 bf = *(const uint2*)(Bs + (nf * 8 + r4) * PJ_BPAD + kk * 8 + 2 * c4);
                mma_tf32(accD[nf], a0, a1, a2, a3, bf.x, bf.y);
            }
        }
    }

    int nlo = n0 + w * 16 + r4;
    if (which == 2) {  // V: fp32 output, no activation scale games
        float* Yb = yv + (size_t)b * (size_t)N_ * CK;
#pragma unroll
        for (int nf = 0; nf < 16; ++nf) {
            int o = nf * 8 + 2 * c4;
            float b0 = __ldg(bias + o), b1 = __ldg(bias + o + 1);
            float2 lo, hi;
            lo.x = accD[nf][0] + b0; lo.y = accD[nf][1] + b1;
            hi.x = accD[nf][2] + b0; hi.y = accD[nf][3] + b1;
            *(float2*)(Yb + (size_t)nlo * CK + o) = lo;
            *(float2*)(Yb + (size_t)(nlo + 8) * CK + o) = hi;
        }
    } else {  // Q/K: relu then (Q only) softmax scale, fp16 output
        float s = (which == 0) ? 0.08838834764831845f : 1.0f;
        __half* Yh = ((which == 0) ? yqh : ykh) + (size_t)b * (size_t)N_ * CK;
#pragma unroll
        for (int nf = 0; nf < 16; ++nf) {
            int o = nf * 8 + 2 * c4;
            float b0 = __ldg(bias + o), b1 = __ldg(bias + o + 1);
            float v0 = fmaxf(accD[nf][0] + b0, 0.f) * s;
            float v1 = fmaxf(accD[nf][1] + b1, 0.f) * s;
            float v2 = fmaxf(accD[nf][2] + b0, 0.f) * s;
            float v3 = fmaxf(accD[nf][3] + b1, 0.f) * s;
            *(uint32_t*)(Yh + (size_t)nlo * CK + o) = pack_h2(v0, v1);
            *(uint32_t*)(Yh + (size_t)(nlo + 8) * CK + o) = pack_h2(v2, v3);
        }
    }
}

// ======== tensor-core output GEMM (tf32, stage both operands) ========
#define GO_PAD 72
#define GO_SMEM ((128 * GO_PAD * 2) * 4)

__global__ __launch_bounds__(256) void gemm_tc_out(
    const float* __restrict__ CTX, const float* __restrict__ WO,
    const float* __restrict__ bo, float* __restrict__ Y) {
    extern __shared__ uint32_t dsm[];
    uint32_t* As = dsm;                // [128 o][72] WO
    uint32_t* Bs = dsm + 128 * GO_PAD; // [128 n][72] CTX

    int b = blockIdx.z;
    int n0 = blockIdx.x * 128, o0 = blockIdx.y * 128;
    const float* Cb = CTX + (size_t)b * N_ * CK;
    float* Yb = Y + (size_t)b * (size_t)COUT * N_;

    int tid = threadIdx.x;
    int w = tid >> 5, lane = tid & 31;
    int r4 = lane >> 2, c4 = lane & 3;

    float accD[16][4];
#pragma unroll
    for (int i = 0; i < 16; ++i)
#pragma unroll
        for (int j = 0; j < 4; ++j) accD[i][j] = 0.f;

    float4 ra[8], rb[8];
#pragma unroll
    for (int i = 0; i < 8; ++i) {
        int idx = tid + i * 256;
        int oo = idx >> 4, cq = idx & 15;
        ra[i] = *(const float4*)(WO + (size_t)(o0 + oo) * CK + cq * 4);
        rb[i] = *(const float4*)(Cb + (size_t)(n0 + oo) * CK + cq * 4);
    }

    for (int c0 = 0; c0 < CK; c0 += 64) {
        __syncthreads();
#pragma unroll
        for (int i = 0; i < 8; ++i) {
            int idx = tid + i * 256;
            int oo = idx >> 4, cq = idx & 15;
            uint32_t* dsta = As + oo * GO_PAD + (cq >> 1) * 8 + (cq & 1);
            dsta[0] = f2tf32(ra[i].x); dsta[2] = f2tf32(ra[i].y);
            dsta[4] = f2tf32(ra[i].z); dsta[6] = f2tf32(ra[i].w);
            uint32_t* dstb = Bs + oo * GO_PAD + (cq >> 1) * 8 + (cq & 1);
            dstb[0] = f2tf32(rb[i].x); dstb[2] = f2tf32(rb[i].y);
            dstb[4] = f2tf32(rb[i].z); dstb[6] = f2tf32(rb[i].w);
        }
        __syncthreads();

        if (c0 + 64 < CK) {
#pragma unroll
            for (int i = 0; i < 8; ++i) {
                int idx = tid + i * 256;
                int oo = idx >> 4, cq = idx & 15;
                ra[i] = *(const float4*)(WO + (size_t)(o0 + oo) * CK + c0 + 64 + cq * 4);
                rb[i] = *(const float4*)(Cb + (size_t)(n0 + oo) * CK + c0 + 64 + cq * 4);
            }
        }

#pragma unroll
        for (int kk = 0; kk < 8; ++kk) {
            uint2 a02 = *(const uint2*)(As + (w * 16 + r4) * GO_PAD + kk * 8 + 2 * c4);
            uint2 a13 = *(const uint2*)(As + (w * 16 + r4 + 8) * GO_PAD + kk * 8 + 2 * c4);
#pragma unroll
            for (int nf = 0; nf < 16; ++nf) {
                uint2 bf = *(const uint2*)(Bs + (nf * 8 + r4) * GO_PAD + kk * 8 + 2 * c4);
                mma_tf32(accD[nf], a02.x, a13.x, a02.y, a13.y, bf.x, bf.y);
            }
        }
    }

    int olo = o0 + w * 16 + r4;
    float blo = __ldg(bo + olo), bhi = __ldg(bo + olo + 8);
#pragma unroll
    for (int nf = 0; nf < 16; ++nf) {
        int n = n0 + nf * 8 + 2 * c4;
        float2 lo, hi;
        lo.x = accD[nf][0] + blo; lo.y = accD[nf][1] + blo;
        hi.x = accD[nf][2] + bhi; hi.y = accD[nf][3] + bhi;
        *(float2*)(Yb + (size_t)olo * N_ + n) = lo;
        *(float2*)(Yb + (size_t)(olo + 8) * N_ + n) = hi;
    }
}

// ---------------- flash attention: fp16 m16n8k16, key-split, double-buffered K ----------------
// Warp w: qgroup=w&3 (32 query rows), khalf=w>>2 (32 of 64 keys/tile).
// P stays in registers (fp16 C-frag == PV A-frag). Vt smem is [d][key] fp16.
#define QPADH  136
#define KPADH  136
#define VTPADH 72
#define KBUFH  (64 * KPADH)
#define OFFK_H (128 * QPADH)
#define OFFV_H (OFFK_H + 2 * KBUFH)
#define SMEM_FLASH ((OFFV_H + 128 * VTPADH) * 2)

__global__ __launch_bounds__(256, 1) void flash_mma(
    const __half* __restrict__ Qh, const __half* __restrict__ Kh,
    const __half* __restrict__ Vth, float* __restrict__ CTX) {
    extern __shared__ __half smh[];
    __half* Qs = smh;
    __half* Ks = smh + OFFK_H;   // two buffers of KBUFH
    __half* Vts = smh + OFFV_H;  // [128 d][72] (64 keys + pad)

    int tid = threadIdx.x;
    int w = tid >> 5, lane = tid & 31;
    int qgroup = w & 3, khalf = w >> 2;
    int r4 = lane >> 2, c4 = lane & 3;
    int b = blockIdx.y;
    int q0 = blockIdx.x * 128;
    const __half* Qb = Qh + ((size_t)b * N_ + q0) * CK;
    const __half* Kb = Kh + (size_t)b * N_ * CK;
    const __half* Vtb = Vth + (size_t)b * CK * N_;

    // prologue: Q tile and K(0) into buffer 0 (fp16 direct copy)
    for (int idx = tid; idx < 128 * 16; idx += 256) {
        int r = idx >> 4, ck = idx & 15;
        *(uint4*)(Qs + r * QPADH + ck * 8) = *(const uint4*)(Qb + (size_t)r * CK + ck * 8);
    }
    for (int idx = tid; idx < 64 * 16; idx += 256) {
        int r = idx >> 4, ck = idx & 15;
        *(uint4*)(Ks + r * KPADH + ck * 8) = *(const uint4*)(Kb + (size_t)r * CK + ck * 8);
    }
    __syncthreads();

    float accO[2][16][4];
#pragma unroll
    for (int rb = 0; rb < 2; ++rb)
#pragma unroll
        for (int i = 0; i < 16; ++i)
#pragma unroll
            for (int j = 0; j < 4; ++j) accO[rb][i][j] = 0.f;
    float l_lo[2] = {0.f, 0.f}, l_hi[2] = {0.f, 0.f};

    const __half* qbase = Qs + (qgroup * 32) * QPADH;
    const int kcol = khalf * 32;
    const int NT = N_ / 64;

    for (int t = 0; t < NT; ++t) {
        const __half* Kcur = Ks + (t & 1) * KBUFH;
        __half* Knxt = Ks + ((t + 1) & 1) * KBUFH;

        // stage Vt(t) in registers; S-compute covers LDG latency
        uint4 vr[4];
        {
            int k0 = t * 64;
#pragma unroll
            for (int i = 0; i < 4; ++i) {
                int idx = tid + i * 256;
                int d = idx >> 3, ck = idx & 7;
                vr[i] = *(const uint4*)(Vtb + (size_t)d * N_ + k0 + ck * 8);
            }
        }

        // S = Q . K^T over this warp's 32 keys (8 k-chunks of 16, 4 n-frags, 2 rowblocks)
        float accS[2][4][4];
#pragma unroll
        for (int rb = 0; rb < 2; ++rb)
#pragma unroll
            for (int i = 0; i < 4; ++i)
#pragma unroll
                for (int j = 0; j < 4; ++j) accS[rb][i][j] = 0.f;
#pragma unroll
        for (int kc = 0; kc < 8; ++kc) {
            int base = kc * 16 + 2 * c4;
            uint32_t a[2][4];
#pragma unroll
            for (int rb = 0; rb < 2; ++rb) {
                const __half* qb = qbase + (rb * 16) * QPADH;
                a[rb][0] = *(const uint32_t*)(qb + r4 * QPADH + base);
                a[rb][1] = *(const uint32_t*)(qb + (r4 + 8) * QPADH + base);
                a[rb][2] = *(const uint32_t*)(qb + r4 * QPADH + base + 8);
                a[rb][3] = *(const uint32_t*)(qb + (r4 + 8) * QPADH + base + 8);
            }
#pragma unroll
            for (int nf = 0; nf < 4; ++nf) {
                const __half* kb = Kcur + (kcol + nf * 8 + r4) * KPADH + base;
                uint32_t b0 = *(const uint32_t*)(kb);
                uint32_t b1 = *(const uint32_t*)(kb + 8);
                mma_f16(accS[0][nf], a[0][0], a[0][1], a[0][2], a[0][3], b0, b1);
                mma_f16(accS[1][nf], a[1][0], a[1][1], a[1][2], a[1][3], b0, b1);
            }
        }

        // P = exp(S - 4) packed into fp16 A-fragments (registers only)
        uint32_t pk[2][4][2];
#pragma unroll
        for (int rb = 0; rb < 2; ++rb) {
            float slo = 0.f, shi = 0.f;
#pragma unroll
            for (int nf = 0; nf < 4; ++nf) {
                float p0 = __expf(accS[rb][nf][0] - 4.f);
                float p1 = __expf(accS[rb][nf][1] - 4.f);
                float p2 = __expf(accS[rb][nf][2] - 4.f);
                float p3 = __expf(accS[rb][nf][3] - 4.f);
                slo += p0 + p1;
                shi += p2 + p3;
                pk[rb][nf][0] = pack_h2(p0, p1);
                pk[rb][nf][1] = pack_h2(p2, p3);
            }
            slo += __shfl_xor_sync(0xffffffffu, slo, 1);
            slo += __shfl_xor_sync(0xffffffffu, slo, 2);
            shi += __shfl_xor_sync(0xffffffffu, shi, 1);
            shi += __shfl_xor_sync(0xffffffffu, shi, 2);
            l_lo[rb] += slo;
            l_hi[rb] += shi;
        }

        // stage K(t+1) in registers (PV covers LDG latency)
        uint4 kr[4];
        bool more = (t + 1 < NT);
        if (more) {
            const __half* Kg = Kb + (size_t)((t + 1) * 64) * CK;
#pragma unroll
            for (int i = 0; i < 4; ++i) {
                int idx = tid + i * 256;
                int r = idx >> 4, ck = idx & 15;
                kr[i] = *(const uint4*)(Kg + (size_t)r * CK + ck * 8);
            }
        }

        // commit Vt(t) to smem
#pragma unroll
        for (int i = 0; i < 4; ++i) {
            int idx = tid + i * 256;
            int d = idx >> 3, ck = idx & 7;
            *(uint4*)(Vts + d * VTPADH + ck * 8) = vr[i];
        }
        __syncthreads();  // B1: Vts complete; all S reads of Kcur done

        // O += P . V (2 k-chunks of 16 keys, 16 d-frags, 2 rowblocks); A from registers
#pragma unroll
        for (int kc = 0; kc < 2; ++kc) {
#pragma unroll
            for (int nf = 0; nf < 16; ++nf) {
                const __half* vb = Vts + (nf * 8 + r4) * VTPADH + kcol + kc * 16 + 2 * c4;
                uint32_t b0 = *(const uint32_t*)(vb);
                uint32_t b1 = *(const uint32_t*)(vb + 8);
                mma_f16(accO[0][nf], pk[0][2 * kc][0], pk[0][2 * kc][1],
                        pk[0][2 * kc + 1][0], pk[0][2 * kc + 1][1], b0, b1);
                mma_f16(accO[1][nf], pk[1][2 * kc][0], pk[1][2 * kc][1],
                        pk[1][2 * kc + 1][0], pk[1][2 * kc + 1][1], b0, b1);
            }
        }

        // commit K(t+1) into the other buffer
        if (more) {
#pragma unroll
            for (int i = 0; i < 4; ++i) {
                int idx = tid + i * 256;
                int r = idx >> 4, ck = idx & 15;
                *(uint4*)(Knxt + r * KPADH + ck * 8) = kr[i];
            }
        }
        __syncthreads();  // B2: Knxt complete; all PV reads of Vts done
    }

    // ---- merge key-halves (overlay scratch on flash smem) ----
    float* Od = (float*)smh;                 // [128][132] fp32 partials
    float* Ld = (float*)smh + 128 * 132;     // [128] partial l
    if (khalf == 1) {
#pragma unroll
        for (int rb = 0; rb < 2; ++rb) {
            int row0 = qgroup * 32 + rb * 16 + r4;
            int row1 = row0 + 8;
#pragma unroll
            for (int nf = 0; nf < 16; ++nf) {
                float2 lo; lo.x = accO[rb][nf][0]; lo.y = accO[rb][nf][1];
                float2 hi; hi.x = accO[rb][nf][2]; hi.y = accO[rb][nf][3];
                *(float2*)(Od + row0 * 132 + nf * 8 + 2 * c4) = lo;
                *(float2*)(Od + row1 * 132 + nf * 8 + 2 * c4) = hi;
            }
            if (c4 == 0) {
                Ld[row0] = l_lo[rb];
                Ld[row1] = l_hi[rb];
            }
        }
    }
    __syncthreads();
    if (khalf == 0) {
#pragma unroll
        for (int rb = 0; rb < 2; ++rb) {
            int row0 = qgroup * 32 + rb * 16 + r4;
            int row1 = row0 + 8;
            float invlo = 1.f / (l_lo[rb] + Ld[row0]);
            float invhi = 1.f / (l_hi[rb] + Ld[row1]);
            float* outlo = CTX + ((size_t)b * N_ + q0 + row0) * CK;
            float* outhi = CTX + ((size_t)b * N_ + q0 + row1) * CK;
#pragma unroll
            for (int nf = 0; nf < 16; ++nf) {
                float2 plo = *(const float2*)(Od + row0 * 132 + nf * 8 + 2 * c4);
                float2 phi = *(const float2*)(Od + row1 * 132 + nf * 8 + 2 * c4);
                float2 lo, hi;
                lo.x = (accO[rb][nf][0] + plo.x) * invlo;
                lo.y = (accO[rb][nf][1] + plo.y) * invlo;
                hi.x = (accO[rb][nf][2] + phi.x) * invhi;
                hi.y = (accO[rb][nf][3] + phi.y) * invhi;
                *(float2*)(outlo + nf * 8 + 2 * c4) = lo;
                *(float2*)(outhi + nf * 8 + 2 * c4) = hi;
            }
        }
    }
}

// ---------------- launch ----------------
extern "C" void kernel_launch(void* const* d_in, const int* in_sizes, int n_in,
                              void* d_out, int out_size) {
    const float* x_enc = (const float*)d_in[0];
    const float* x_dec = (const float*)d_in[1];
    const float* wk    = (const float*)d_in[2];
    const float* bk    = (const float*)d_in[3];
    const float* gk    = (const float*)d_in[4];
    const float* betak = (const float*)d_in[5];
    const float* mk    = (const float*)d_in[6];
    const float* vk    = (const float*)d_in[7];
    const float* wq    = (const float*)d_in[8];
    const float* bq    = (const float*)d_in[9];
    const float* gq    = (const float*)d_in[10];
    const float* betaq = (const float*)d_in[11];
    const float* mq    = (const float*)d_in[12];
    const float* vq    = (const float*)d_in[13];
    const float* wv    = (const float*)d_in[14];
    const float* bv    = (const float*)d_in[15];
    const float* wo    = (const float*)d_in[16];
    const float* bo    = (const float*)d_in[17];
    float* out = (float*)d_out;

    __half *pqh, *pkh, *pvth;
    float *pv, *pctx, *pwq, *pwk, *pbq, *pbk;
    cudaGetSymbolAddress((void**)&pqh, g_qh);
    cudaGetSymbolAddress((void**)&pkh, g_kh);
    cudaGetSymbolAddress((void**)&pvth, g_vth);
    cudaGetSymbolAddress((void**)&pv, g_v);
    cudaGetSymbolAddress((void**)&pctx, g_ctx);
    cudaGetSymbolAddress((void**)&pwq, g_wq);
    cudaGetSymbolAddress((void**)&pwk, g_wk);
    cudaGetSymbolAddress((void**)&pbq, g_bq);
    cudaGetSymbolAddress((void**)&pbk, g_bk);

    prep_kernel<<<(CK * CIN + 255) / 256, 256>>>(wk, bk, gk, betak, mk, vk,
                                                 wq, bq, gq, betaq, mq, vq);

    cudaFuncSetAttribute(gemm_tc_proj3, cudaFuncAttributeMaxDynamicSharedMemorySize, PJ_SMEM);
    cudaFuncSetAttribute(gemm_tc_out, cudaFuncAttributeMaxDynamicSharedMemorySize, GO_SMEM);
    cudaFuncSetAttribute(flash_mma, cudaFuncAttributeMaxDynamicSharedMemorySize, SMEM_FLASH);

    gemm_tc_proj3<<<dim3(N_ / 128, 3, B_), 256, PJ_SMEM>>>(
        x_dec, x_enc, pwq, pwk, wv, pbq, pbk, bv, pqh, pkh, pv);

    transpose_v<<<dim3(N_ / 32, CK / 32, B_), dim3(32, 8)>>>(pv, pvth);

    flash_mma<<<dim3(N_ / 128, B_), 256, SMEM_FLASH>>>(pqh, pkh, pvth, pctx);

    gemm_tc_out<<<dim3(N_ / 128, COUT / 128, B_), 256, GO_SMEM>>>(pctx, wo, bo, out);
}

// round 10
// speedup vs baseline: 2.4450x; 1.0466x over previous
#include <cuda_runtime.h>
#include <cuda_fp16.h>
#include <cstdint>

#define B_   4
#define N_   4096
#define CIN  256
#define CK   128
#define COUT 256

// ---------------- scratch (no allocs allowed) ----------------
__device__ __half g_qh[B_ * N_ * CK];   // [b][n][128] fp16, pre-scaled by 1/sqrt(128)
__device__ __half g_kh[B_ * N_ * CK];   // [b][n][128] fp16
__device__ float  g_v[B_ * N_ * CK];    // [b][n][128] fp32 (transpose input)
__device__ __half g_vth[B_ * CK * N_];  // [b][d][n] fp16 (transposed V)
__device__ float  g_ctx[B_ * N_ * CK];  // [b][n][128]
__device__ float  g_wq[CK * CIN];
__device__ float  g_wk[CK * CIN];
__device__ float  g_bq[CK];
__device__ float  g_bk[CK];

// ================= helpers =================
__device__ __forceinline__ uint32_t f2tf32(float f) {
    uint32_t u;
    asm("cvt.rna.tf32.f32 %0, %1;" : "=r"(u) : "f"(f));
    return u;
}
__device__ __forceinline__ uint32_t pack_h2(float lo, float hi) {
    __half2 h = __floats2half2_rn(lo, hi);
    return *(uint32_t*)&h;
}
__device__ __forceinline__ void mma_tf32(float* d, uint32_t a0, uint32_t a1,
                                         uint32_t a2, uint32_t a3,
                                         uint32_t b0, uint32_t b1) {
    asm volatile(
        "mma.sync.aligned.m16n8k8.row.col.f32.tf32.tf32.f32 "
        "{%0,%1,%2,%3}, {%4,%5,%6,%7}, {%8,%9}, {%0,%1,%2,%3};"
        : "+f"(d[0]), "+f"(d[1]), "+f"(d[2]), "+f"(d[3])
        : "r"(a0), "r"(a1), "r"(a2), "r"(a3), "r"(b0), "r"(b1));
}
__device__ __forceinline__ void mma_f16(float* d, uint32_t a0, uint32_t a1,
                                        uint32_t a2, uint32_t a3,
                                        uint32_t b0, uint32_t b1) {
    asm volatile(
        "mma.sync.aligned.m16n8k16.row.col.f32.f16.f16.f32 "
        "{%0,%1,%2,%3}, {%4,%5,%6,%7}, {%8,%9}, {%0,%1,%2,%3};"
        : "+f"(d[0]), "+f"(d[1]), "+f"(d[2]), "+f"(d[3])
        : "r"(a0), "r"(a1), "r"(a2), "r"(a3), "r"(b0), "r"(b1));
}
__device__ __forceinline__ void ldsm_x4(uint32_t& r0, uint32_t& r1, uint32_t& r2,
                                        uint32_t& r3, uint32_t addr) {
    asm volatile("ldmatrix.sync.aligned.m8n8.x4.shared.b16 {%0,%1,%2,%3}, [%4];"
                 : "=r"(r0), "=r"(r1), "=r"(r2), "=r"(r3) : "r"(addr));
}
#define CP_ASYNC16(dst, src) \
    asm volatile("cp.async.cg.shared.global [%0], [%1], 16;" :: "r"(dst), "l"(src) : "memory")
#define CP_COMMIT() asm volatile("cp.async.commit_group;" ::: "memory")
#define CP_WAIT1()  asm volatile("cp.async.wait_group 1;" ::: "memory")
#define CP_WAIT0()  asm volatile("cp.async.wait_group 0;" ::: "memory")

// ---------------- BN folding ----------------
__global__ void prep_kernel(const float* __restrict__ wk, const float* __restrict__ bk,
                            const float* __restrict__ gk, const float* __restrict__ betak,
                            const float* __restrict__ mk, const float* __restrict__ vk,
                            const float* __restrict__ wq, const float* __restrict__ bq,
                            const float* __restrict__ gq, const float* __restrict__ betaq,
                            const float* __restrict__ mq, const float* __restrict__ vq) {
    int idx = blockIdx.x * blockDim.x + threadIdx.x;
    if (idx >= CK * CIN) return;
    int o = idx / CIN;
    float sk = gk[o] * rsqrtf(vk[o] + 1e-5f);
    float sq = gq[o] * rsqrtf(vq[o] + 1e-5f);
    g_wk[idx] = wk[idx] * sk;
    g_wq[idx] = wq[idx] * sq;
    if ((idx % CIN) == 0) {
        g_bk[o] = (bk[o] - mk[o]) * sk + betak[o];
        g_bq[o] = (bq[o] - mq[o]) * sq + betaq[o];
    }
}

// ---------------- V transpose: [b][n][128] fp32 -> [b][128][n] fp16 ----------------
__global__ __launch_bounds__(256) void transpose_v(const float* __restrict__ V,
                                                   __half* __restrict__ Vt) {
    __shared__ float tile[32][33];
    int b = blockIdx.z;
    int n0 = blockIdx.x * 32, d0 = blockIdx.y * 32;
    const float* Vb = V + (size_t)b * N_ * CK;
    __half* Tb = Vt + (size_t)b * CK * N_;
    int tx = threadIdx.x, ty = threadIdx.y;  // 32 x 8
#pragma unroll
    for (int i = 0; i < 32; i += 8)
        tile[ty + i][tx] = Vb[(size_t)(n0 + ty + i) * CK + d0 + tx];
    __syncthreads();
#pragma unroll
    for (int i = 0; i < 32; i += 8)
        Tb[(size_t)(d0 + ty + i) * N_ + n0 + tx] = __float2half(tile[tx][ty + i]);
}

// ======== fused 3-way projection GEMM (tf32 mma; Q/K epilogues emit fp16) ========
#define PJ_APAD 136
#define PJ_BPAD 72
#define PJ_SMEM ((64 * PJ_APAD + 128 * PJ_BPAD) * 4)

__global__ __launch_bounds__(256, 2) void gemm_tc_proj3(
    const float* __restrict__ xdec, const float* __restrict__ xenc,
    const float* __restrict__ wq, const float* __restrict__ wk,
    const float* __restrict__ wv,
    const float* __restrict__ bq, const float* __restrict__ bk,
    const float* __restrict__ bv,
    __half* __restrict__ yqh, __half* __restrict__ ykh, float* __restrict__ yv) {
    extern __shared__ uint32_t dsm[];
    uint32_t* As = dsm;                 // [64 c][136 n] tf32
    uint32_t* Bs = dsm + 64 * PJ_APAD;  // [128 o][72 interleaved c] tf32

    int which = blockIdx.y;
    const float* X = (which == 0) ? xdec : xenc;
    const float* W = (which == 0) ? wq : (which == 1) ? wk : wv;
    const float* bias = (which == 0) ? bq : (which == 1) ? bk : bv;

    int b = blockIdx.z;
    int n0 = blockIdx.x * 128;
    const float* Xb = X + (size_t)b * CIN * N_;

    int tid = threadIdx.x;
    int w = tid >> 5, lane = tid & 31;
    int r4 = lane >> 2, c4 = lane & 3;

    float accD[16][4];
#pragma unroll
    for (int i = 0; i < 16; ++i)
#pragma unroll
        for (int j = 0; j < 4; ++j) accD[i][j] = 0.f;

    float4 ra[8];
#pragma unroll
    for (int i = 0; i < 8; ++i) {
        int idx = tid + i * 256;
        int cc = idx >> 5, nq = idx & 31;
        ra[i] = *(const float4*)(Xb + (size_t)cc * N_ + n0 + nq * 4);
    }

    for (int c0 = 0; c0 < CIN; c0 += 64) {
        __syncthreads();
#pragma unroll
        for (int i = 0; i < 8; ++i) {
            int idx = tid + i * 256;
            int cc = idx >> 5, nq = idx & 31;
            uint4 u;
            u.x = f2tf32(ra[i].x); u.y = f2tf32(ra[i].y);
            u.z = f2tf32(ra[i].z); u.w = f2tf32(ra[i].w);
            *(uint4*)(As + cc * PJ_APAD + nq * 4) = u;
        }
#pragma unroll
        for (int i = 0; i < 8; ++i) {
            int idx = tid + i * 256;
            int oo = idx >> 4, cq = idx & 15;
            float4 v = *(const float4*)(W + (size_t)oo * CIN + c0 + cq * 4);
            uint32_t* dst = Bs + oo * PJ_BPAD + (cq >> 1) * 8 + (cq & 1);
            dst[0] = f2tf32(v.x); dst[2] = f2tf32(v.y);
            dst[4] = f2tf32(v.z); dst[6] = f2tf32(v.w);
        }
        __syncthreads();

        if (c0 + 64 < CIN) {
#pragma unroll
            for (int i = 0; i < 8; ++i) {
                int idx = tid + i * 256;
                int cc = idx >> 5, nq = idx & 31;
                ra[i] = *(const float4*)(Xb + (size_t)(c0 + 64 + cc) * N_ + n0 + nq * 4);
            }
        }

#pragma unroll
        for (int kk = 0; kk < 8; ++kk) {
            uint32_t a0 = As[(kk * 8 + c4) * PJ_APAD + w * 16 + r4];
            uint32_t a1 = As[(kk * 8 + c4) * PJ_APAD + w * 16 + r4 + 8];
            uint32_t a2 = As[(kk * 8 + c4 + 4) * PJ_APAD + w * 16 + r4];
            uint32_t a3 = As[(kk * 8 + c4 + 4) * PJ_APAD + w * 16 + r4 + 8];
#pragma unroll
            for (int nf = 0; nf < 16; ++nf) {
                uint2 bf = *(const uint2*)(Bs + (nf * 8 + r4) * PJ_BPAD + kk * 8 + 2 * c4);
                mma_tf32(accD[nf], a0, a1, a2, a3, bf.x, bf.y);
            }
        }
    }

    int nlo = n0 + w * 16 + r4;
    if (which == 2) {
        float* Yb = yv + (size_t)b * (size_t)N_ * CK;
#pragma unroll
        for (int nf = 0; nf < 16; ++nf) {
            int o = nf * 8 + 2 * c4;
            float b0 = __ldg(bias + o), b1 = __ldg(bias + o + 1);
            float2 lo, hi;
            lo.x = accD[nf][0] + b0; lo.y = accD[nf][1] + b1;
            hi.x = accD[nf][2] + b0; hi.y = accD[nf][3] + b1;
            *(float2*)(Yb + (size_t)nlo * CK + o) = lo;
            *(float2*)(Yb + (size_t)(nlo + 8) * CK + o) = hi;
        }
    } else {
        float s = (which == 0) ? 0.08838834764831845f : 1.0f;
        __half* Yh = ((which == 0) ? yqh : ykh) + (size_t)b * (size_t)N_ * CK;
#pragma unroll
        for (int nf = 0; nf < 16; ++nf) {
            int o = nf * 8 + 2 * c4;
            float b0 = __ldg(bias + o), b1 = __ldg(bias + o + 1);
            float v0 = fmaxf(accD[nf][0] + b0, 0.f) * s;
            float v1 = fmaxf(accD[nf][1] + b1, 0.f) * s;
            float v2 = fmaxf(accD[nf][2] + b0, 0.f) * s;
            float v3 = fmaxf(accD[nf][3] + b1, 0.f) * s;
            *(uint32_t*)(Yh + (size_t)nlo * CK + o) = pack_h2(v0, v1);
            *(uint32_t*)(Yh + (size_t)(nlo + 8) * CK + o) = pack_h2(v2, v3);
        }
    }
}

// ======== tensor-core output GEMM (tf32, stage both operands) ========
#define GO_PAD 72
#define GO_SMEM ((128 * GO_PAD * 2) * 4)

__global__ __launch_bounds__(256) void gemm_tc_out(
    const float* __restrict__ CTX, const float* __restrict__ WO,
    const float* __restrict__ bo, float* __restrict__ Y) {
    extern __shared__ uint32_t dsm[];
    uint32_t* As = dsm;                // [128 o][72] WO
    uint32_t* Bs = dsm + 128 * GO_PAD; // [128 n][72] CTX

    int b = blockIdx.z;
    int n0 = blockIdx.x * 128, o0 = blockIdx.y * 128;
    const float* Cb = CTX + (size_t)b * N_ * CK;
    float* Yb = Y + (size_t)b * (size_t)COUT * N_;

    int tid = threadIdx.x;
    int w = tid >> 5, lane = tid & 31;
    int r4 = lane >> 2, c4 = lane & 3;

    float accD[16][4];
#pragma unroll
    for (int i = 0; i < 16; ++i)
#pragma unroll
        for (int j = 0; j < 4; ++j) accD[i][j] = 0.f;

    float4 ra[8], rb[8];
#pragma unroll
    for (int i = 0; i < 8; ++i) {
        int idx = tid + i * 256;
        int oo = idx >> 4, cq = idx & 15;
        ra[i] = *(const float4*)(WO + (size_t)(o0 + oo) * CK + cq * 4);
        rb[i] = *(const float4*)(Cb + (size_t)(n0 + oo) * CK + cq * 4);
    }

    for (int c0 = 0; c0 < CK; c0 += 64) {
        __syncthreads();
#pragma unroll
        for (int i = 0; i < 8; ++i) {
            int idx = tid + i * 256;
            int oo = idx >> 4, cq = idx & 15;
            uint32_t* dsta = As + oo * GO_PAD + (cq >> 1) * 8 + (cq & 1);
            dsta[0] = f2tf32(ra[i].x); dsta[2] = f2tf32(ra[i].y);
            dsta[4] = f2tf32(ra[i].z); dsta[6] = f2tf32(ra[i].w);
            uint32_t* dstb = Bs + oo * GO_PAD + (cq >> 1) * 8 + (cq & 1);
            dstb[0] = f2tf32(rb[i].x); dstb[2] = f2tf32(rb[i].y);
            dstb[4] = f2tf32(rb[i].z); dstb[6] = f2tf32(rb[i].w);
        }
        __syncthreads();

        if (c0 + 64 < CK) {
#pragma unroll
            for (int i = 0; i < 8; ++i) {
                int idx = tid + i * 256;
                int oo = idx >> 4, cq = idx & 15;
                ra[i] = *(const float4*)(WO + (size_t)(o0 + oo) * CK + c0 + 64 + cq * 4);
                rb[i] = *(const float4*)(Cb + (size_t)(n0 + oo) * CK + c0 + 64 + cq * 4);
            }
        }

#pragma unroll
        for (int kk = 0; kk < 8; ++kk) {
            uint2 a02 = *(const uint2*)(As + (w * 16 + r4) * GO_PAD + kk * 8 + 2 * c4);
            uint2 a13 = *(const uint2*)(As + (w * 16 + r4 + 8) * GO_PAD + kk * 8 + 2 * c4);
#pragma unroll
            for (int nf = 0; nf < 16; ++nf) {
                uint2 bf = *(const uint2*)(Bs + (nf * 8 + r4) * GO_PAD + kk * 8 + 2 * c4);
                mma_tf32(accD[nf], a02.x, a13.x, a02.y, a13.y, bf.x, bf.y);
            }
        }
    }

    int olo = o0 + w * 16 + r4;
    float blo = __ldg(bo + olo), bhi = __ldg(bo + olo + 8);
#pragma unroll
    for (int nf = 0; nf < 16; ++nf) {
        int n = n0 + nf * 8 + 2 * c4;
        float2 lo, hi;
        lo.x = accD[nf][0] + blo; lo.y = accD[nf][1] + blo;
        hi.x = accD[nf][2] + bhi; hi.y = accD[nf][3] + bhi;
        *(float2*)(Yb + (size_t)olo * N_ + n) = lo;
        *(float2*)(Yb + (size_t)(olo + 8) * N_ + n) = hi;
    }
}

// ---------------- flash attention: fp16 + ldmatrix + cp.async ----------------
// Warp w: qgroup=w&3 (32 query rows), khalf=w>>2 (32 of 64 keys/tile).
// P in registers; K double-buffered via cp.async; V streamed via cp.async.
#define QPADH  136
#define KPADH  136
#define VTPADH 72
#define KBUFH  (64 * KPADH)
#define OFFK_H (128 * QPADH)
#define OFFV_H (OFFK_H + 2 * KBUFH)
#define SMEM_FLASH ((OFFV_H + 128 * VTPADH) * 2)

__global__ __launch_bounds__(256, 1) void flash_mma(
    const __half* __restrict__ Qh, const __half* __restrict__ Kh,
    const __half* __restrict__ Vth, float* __restrict__ CTX) {
    extern __shared__ __half smh[];
    __half* Qs = smh;
    __half* Ks = smh + OFFK_H;   // two buffers of KBUFH
    __half* Vts = smh + OFFV_H;  // [128 d][72]

    int tid = threadIdx.x;
    int w = tid >> 5, lane = tid & 31;
    int qgroup = w & 3, khalf = w >> 2;
    int r4 = lane >> 2, c4 = lane & 3;
    int b = blockIdx.y;
    int q0 = blockIdx.x * 128;
    const __half* Qb = Qh + ((size_t)b * N_ + q0) * CK;
    const __half* Kb = Kh + (size_t)b * N_ * CK;
    const __half* Vtb = Vth + (size_t)b * CK * N_;

    uint32_t qs_u = (uint32_t)__cvta_generic_to_shared(Qs);
    uint32_t ks_u = (uint32_t)__cvta_generic_to_shared(Ks);
    uint32_t vts_u = (uint32_t)__cvta_generic_to_shared(Vts);

    // ldmatrix lane->row mappings (addresses in halfs, *2 for bytes)
    int arow = (lane & 7) + ((lane >> 3) & 1) * 8;  // A: row within 16
    int ak8 = (lane >> 4) * 8;                       // A: k-offset 0/8
    int brow = (lane & 7) + ((lane >> 4) & 1) * 8;  // B: row within nf-pair
    int bk8 = ((lane >> 3) & 1) * 8;                 // B: k-offset 0/8

    // prologue: Q tile and K(0) into buffer 0
    for (int idx = tid; idx < 128 * 16; idx += 256) {
        int r = idx >> 4, ck = idx & 15;
        *(uint4*)(Qs + r * QPADH + ck * 8) = *(const uint4*)(Qb + (size_t)r * CK + ck * 8);
    }
    for (int idx = tid; idx < 64 * 16; idx += 256) {
        int r = idx >> 4, ck = idx & 15;
        *(uint4*)(Ks + r * KPADH + ck * 8) = *(const uint4*)(Kb + (size_t)r * CK + ck * 8);
    }
    __syncthreads();

    float accO[2][16][4];
#pragma unroll
    for (int rb = 0; rb < 2; ++rb)
#pragma unroll
        for (int i = 0; i < 16; ++i)
#pragma unroll
            for (int j = 0; j < 4; ++j) accO[rb][i][j] = 0.f;
    float l_lo[2] = {0.f, 0.f}, l_hi[2] = {0.f, 0.f};

    const int kcol = khalf * 32;
    const int NT = N_ / 64;

    // per-lane ldmatrix base addresses (bytes)
    uint32_t qa_base0 = qs_u + (((qgroup * 32 + arow) * QPADH) + ak8) * 2;         // rb=0
    uint32_t qa_base1 = qa_base0 + (16 * QPADH) * 2;                               // rb=1
    uint32_t kb_base = ((kcol + brow) * KPADH + bk8) * 2;                          // + buffer base
    uint32_t vb_base = vts_u + ((brow) * VTPADH + kcol + bk8) * 2;                 // + nf*8*VTPADH*2

    // cp.async smem destinations (this thread's chunks)
    // V: idx = tid + i*256 -> d = idx>>3, ck = idx&7
    // K: idx = tid + i*256 -> r = idx>>4, ck = idx&15

    for (int t = 0; t < NT; ++t) {
        uint32_t kcur_u = ks_u + (t & 1) * (KBUFH * 2);
        uint32_t knxt_u = ks_u + ((t + 1) & 1) * (KBUFH * 2);

        // issue V(t) cp.async (group 1 of this tile)
        {
            int k0 = t * 64;
#pragma unroll
            for (int i = 0; i < 4; ++i) {
                int idx = tid + i * 256;
                int d = idx >> 3, ck = idx & 7;
                CP_ASYNC16(vts_u + (d * VTPADH + ck * 8) * 2,
                           Vtb + (size_t)d * N_ + k0 + ck * 8);
            }
            CP_COMMIT();
        }

        // S = Q . K^T over this warp's 32 keys (8 k-chunks, 4 n-frags, 2 rowblocks)
        float accS[2][4][4];
#pragma unroll
        for (int rb = 0; rb < 2; ++rb)
#pragma unroll
            for (int i = 0; i < 4; ++i)
#pragma unroll
                for (int j = 0; j < 4; ++j) accS[rb][i][j] = 0.f;
#pragma unroll
        for (int kc = 0; kc < 8; ++kc) {
            uint32_t a0[2], a1[2], a2[2], a3[2];
            ldsm_x4(a0[0], a1[0], a2[0], a3[0], qa_base0 + kc * 32);
            ldsm_x4(a0[1], a1[1], a2[1], a3[1], qa_base1 + kc * 32);
            uint32_t b00, b01, b10, b11;
            // nf = 0,1
            ldsm_x4(b00, b01, b10, b11, kcur_u + kb_base + kc * 32);
            mma_f16(accS[0][0], a0[0], a1[0], a2[0], a3[0], b00, b01);
            mma_f16(accS[1][0], a0[1], a1[1], a2[1], a3[1], b00, b01);
            mma_f16(accS[0][1], a0[0], a1[0], a2[0], a3[0], b10, b11);
            mma_f16(accS[1][1], a0[1], a1[1], a2[1], a3[1], b10, b11);
            // nf = 2,3
            ldsm_x4(b00, b01, b10, b11, kcur_u + kb_base + (16 * KPADH) * 2 + kc * 32);
            mma_f16(accS[0][2], a0[0], a1[0], a2[0], a3[0], b00, b01);
            mma_f16(accS[1][2], a0[1], a1[1], a2[1], a3[1], b00, b01);
            mma_f16(accS[0][3], a0[0], a1[0], a2[0], a3[0], b10, b11);
            mma_f16(accS[1][3], a0[1], a1[1], a2[1], a3[1], b10, b11);
        }

        // P = exp(S - 4) packed into fp16 A-fragments (registers only)
        uint32_t pk[2][4][2];
#pragma unroll
        for (int rb = 0; rb < 2; ++rb) {
            float slo = 0.f, shi = 0.f;
#pragma unroll
            for (int nf = 0; nf < 4; ++nf) {
                float p0 = __expf(accS[rb][nf][0] - 4.f);
                float p1 = __expf(accS[rb][nf][1] - 4.f);
                float p2 = __expf(accS[rb][nf][2] - 4.f);
                float p3 = __expf(accS[rb][nf][3] - 4.f);
                slo += p0 + p1;
                shi += p2 + p3;
                pk[rb][nf][0] = pack_h2(p0, p1);
                pk[rb][nf][1] = pack_h2(p2, p3);
            }
            slo += __shfl_xor_sync(0xffffffffu, slo, 1);
            slo += __shfl_xor_sync(0xffffffffu, slo, 2);
            shi += __shfl_xor_sync(0xffffffffu, shi, 1);
            shi += __shfl_xor_sync(0xffffffffu, shi, 2);
            l_lo[rb] += slo;
            l_hi[rb] += shi;
        }

        // issue K(t+1) cp.async (group 2; empty group on last tile)
        if (t + 1 < NT) {
            const __half* Kg = Kb + (size_t)((t + 1) * 64) * CK;
#pragma unroll
            for (int i = 0; i < 4; ++i) {
                int idx = tid + i * 256;
                int r = idx >> 4, ck = idx & 15;
                CP_ASYNC16(knxt_u + (r * KPADH + ck * 8) * 2,
                           Kg + (size_t)r * CK + ck * 8);
            }
        }
        CP_COMMIT();

        CP_WAIT1();       // V(t) group complete (K may still fly)
        __syncthreads();  // B1: Vts visible to all; all S reads of Kcur done

        // O += P . V (2 k-chunks of 16 keys, 16 d-frags, 2 rowblocks)
#pragma unroll
        for (int kc = 0; kc < 2; ++kc) {
#pragma unroll
            for (int nf = 0; nf < 16; nf += 2) {
                uint32_t b00, b01, b10, b11;
                ldsm_x4(b00, b01, b10, b11,
                        vb_base + (nf * 8 * VTPADH) * 2 + kc * 32);
                mma_f16(accO[0][nf], pk[0][2 * kc][0], pk[0][2 * kc][1],
                        pk[0][2 * kc + 1][0], pk[0][2 * kc + 1][1], b00, b01);
                mma_f16(accO[1][nf], pk[1][2 * kc][0], pk[1][2 * kc][1],
                        pk[1][2 * kc + 1][0], pk[1][2 * kc + 1][1], b00, b01);
                mma_f16(accO[0][nf + 1], pk[0][2 * kc][0], pk[0][2 * kc][1],
                        pk[0][2 * kc + 1][0], pk[0][2 * kc + 1][1], b10, b11);
                mma_f16(accO[1][nf + 1], pk[1][2 * kc][0], pk[1][2 * kc][1],
                        pk[1][2 * kc + 1][0], pk[1][2 * kc + 1][1], b10, b11);
            }
        }

        CP_WAIT0();       // K(t+1) complete
        __syncthreads();  // B2: Knxt visible; all PV reads of Vts done
    }

    // ---- merge key-halves (overlay scratch on flash smem) ----
    float* Od = (float*)smh;              // [128][132] fp32 partials
    float* Ld = (float*)smh + 128 * 132;  // [128] partial l
    if (khalf == 1) {
#pragma unroll
        for (int rb = 0; rb < 2; ++rb) {
            int row0 = qgroup * 32 + rb * 16 + r4;
            int row1 = row0 + 8;
#pragma unroll
            for (int nf = 0; nf < 16; ++nf) {
                float2 lo; lo.x = accO[rb][nf][0]; lo.y = accO[rb][nf][1];
                float2 hi; hi.x = accO[rb][nf][2]; hi.y = accO[rb][nf][3];
                *(float2*)(Od + row0 * 132 + nf * 8 + 2 * c4) = lo;
                *(float2*)(Od + row1 * 132 + nf * 8 + 2 * c4) = hi;
            }
            if (c4 == 0) {
                Ld[row0] = l_lo[rb];
                Ld[row1] = l_hi[rb];
            }
        }
    }
    __syncthreads();
    if (khalf == 0) {
#pragma unroll
        for (int rb = 0; rb < 2; ++rb) {
            int row0 = qgroup * 32 + rb * 16 + r4;
            int row1 = row0 + 8;
            float invlo = 1.f / (l_lo[rb] + Ld[row0]);
            float invhi = 1.f / (l_hi[rb] + Ld[row1]);
            float* outlo = CTX + ((size_t)b * N_ + q0 + row0) * CK;
            float* outhi = CTX + ((size_t)b * N_ + q0 + row1) * CK;
#pragma unroll
            for (int nf = 0; nf < 16; ++nf) {
                float2 plo = *(const float2*)(Od + row0 * 132 + nf * 8 + 2 * c4);
                float2 phi = *(const float2*)(Od + row1 * 132 + nf * 8 + 2 * c4);
                float2 lo, hi;
                lo.x = (accO[rb][nf][0] + plo.x) * invlo;
                lo.y = (accO[rb][nf][1] + plo.y) * invlo;
                hi.x = (accO[rb][nf][2] + phi.x) * invhi;
                hi.y = (accO[rb][nf][3] + phi.y) * invhi;
                *(float2*)(outlo + nf * 8 + 2 * c4) = lo;
                *(float2*)(outhi + nf * 8 + 2 * c4) = hi;
            }
        }
    }
}

// ---------------- launch ----------------
extern "C" void kernel_launch(void* const* d_in, const int* in_sizes, int n_in,
                              void* d_out, int out_size) {
    const float* x_enc = (const float*)d_in[0];
    const float* x_dec = (const float*)d_in[1];
    const float* wk    = (const float*)d_in[2];
    const float* bk    = (const float*)d_in[3];
    const float* gk    = (const float*)d_in[4];
    const float* betak = (const float*)d_in[5];
    const float* mk    = (const float*)d_in[6];
    const float* vk    = (const float*)d_in[7];
    const float* wq    = (const float*)d_in[8];
    const float* bq    = (const float*)d_in[9];
    const float* gq    = (const float*)d_in[10];
    const float* betaq = (const float*)d_in[11];
    const float* mq    = (const float*)d_in[12];
    const float* vq    = (const float*)d_in[13];
    const float* wv    = (const float*)d_in[14];
    const float* bv    = (const float*)d_in[15];
    const float* wo    = (const float*)d_in[16];
    const float* bo    = (const float*)d_in[17];
    float* out = (float*)d_out;

    __half *pqh, *pkh, *pvth;
    float *pv, *pctx, *pwq, *pwk, *pbq, *pbk;
    cudaGetSymbolAddress((void**)&pqh, g_qh);
    cudaGetSymbolAddress((void**)&pkh, g_kh);
    cudaGetSymbolAddress((void**)&pvth, g_vth);
    cudaGetSymbolAddress((void**)&pv, g_v);
    cudaGetSymbolAddress((void**)&pctx, g_ctx);
    cudaGetSymbolAddress((void**)&pwq, g_wq);
    cudaGetSymbolAddress((void**)&pwk, g_wk);
    cudaGetSymbolAddress((void**)&pbq, g_bq);
    cudaGetSymbolAddress((void**)&pbk, g_bk);

    prep_kernel<<<(CK * CIN + 255) / 256, 256>>>(wk, bk, gk, betak, mk, vk,
                                                 wq, bq, gq, betaq, mq, vq);

    cudaFuncSetAttribute(gemm_tc_proj3, cudaFuncAttributeMaxDynamicSharedMemorySize, PJ_SMEM);
    cudaFuncSetAttribute(gemm_tc_out, cudaFuncAttributeMaxDynamicSharedMemorySize, GO_SMEM);
    cudaFuncSetAttribute(flash_mma, cudaFuncAttributeMaxDynamicSharedMemorySize, SMEM_FLASH);

    gemm_tc_proj3<<<dim3(N_ / 128, 3, B_), 256, PJ_SMEM>>>(
        x_dec, x_enc, pwq, pwk, wv, pbq, pbk, bv, pqh, pkh, pv);

    transpose_v<<<dim3(N_ / 32, CK / 32, B_), dim3(32, 8)>>>(pv, pvth);

    flash_mma<<<dim3(N_ / 128, B_), 256, SMEM_FLASH>>>(pqh, pkh, pvth, pctx);

    gemm_tc_out<<<dim3(N_ / 128, COUT / 128, B_), 256, GO_SMEM>>>(pctx, wo, bo, out);
}